// round 5
// baseline (speedup 1.0000x reference)
#include <cuda_runtime.h>
#include <math.h>
#include <stdint.h>

// ---------------- problem constants ----------------
#define BATCH 4
#define CCH   512
#define C8    64
#define NPIX  4096           // 64*64

// ---------------- scratch (device globals; allocation-free) ----------------
__device__ float g_qp[BATCH * C8 * NPIX];
__device__ float g_kp[BATCH * C8 * NPIX];
__device__ float g_vp[BATCH * CCH * NPIX];
__device__ float g_qc[BATCH * C8 * NPIX];
__device__ float g_kc[BATCH * C8 * NPIX];
__device__ float g_vc[BATCH * CCH * NPIX];
__device__ float g_attn[(size_t)BATCH * NPIX * NPIX];
__device__ float g_ec[BATCH * CCH * CCH];
__device__ float g_outp[BATCH * CCH * NPIX];
__device__ float g_outc[BATCH * CCH * NPIX];

#define MMA_TF32(acc, af, bf)                                               \
    asm volatile(                                                           \
        "mma.sync.aligned.m16n8k8.row.col.f32.tf32.tf32.f32 "               \
        "{%0,%1,%2,%3},{%4,%5,%6,%7},{%8,%9},{%0,%1,%2,%3};"                \
        : "+f"(acc[0]), "+f"(acc[1]), "+f"(acc[2]), "+f"(acc[3])            \
        : "r"(af[0]), "r"(af[1]), "r"(af[2]), "r"(af[3]),                   \
          "r"(bf[0]), "r"(bf[1]))

// ---------------- tf32 tensor-core GEMM ----------------
// C[M,N] = A*B (+bias per row).  TA: A stored [K,M]; else [M,K].
// TB: B stored [N,K]; else [K,N].  Requires: K%16==0, N%128==0.
// CTA tile 128x128, BK=16, 8 warps of 64x32, double-buffered smem.
// fp32 bits fed directly to tf32 HMMA (hardware truncation, cutlass fast path).
template<bool TA, bool TB, bool BIAS>
__global__ void __launch_bounds__(256, 2)
gemm_tc(const float* __restrict__ A, const float* __restrict__ B,
        const float* __restrict__ bias, float* __restrict__ C,
        int M, int N, int K,
        long long aStr, long long bStr, long long cStr)
{
    constexpr int BM = 128, BN = 128, BK = 16;
    __shared__ uint32_t As[2][BK][BM + 8];
    __shared__ uint32_t Bs[2][BK][BN + 8];

    const float* Ab = A + (long long)blockIdx.z * aStr;
    const float* Bb = B + (long long)blockIdx.z * bStr;
    float*       Cb = C + (long long)blockIdx.z * cStr;

    const int bm = blockIdx.y * BM;
    const int bn = blockIdx.x * BN;
    const int tid = threadIdx.x;
    const int lane = tid & 31;
    const int grp  = lane >> 2;      // 0..7
    const int tig  = lane & 3;       // 0..3
    const int warpId = tid >> 5;
    const int warpM  = warpId >> 2;  // 0..1  (64-row slabs)
    const int warpN  = warpId & 3;   // 0..3  (32-col slabs)

    float acc[4][4][4];
#pragma unroll
    for (int mi = 0; mi < 4; mi++)
#pragma unroll
        for (int ni = 0; ni < 4; ni++)
#pragma unroll
            for (int r = 0; r < 4; r++) acc[mi][ni][r] = 0.0f;

    float4 ra[2], rb[2];

    auto ldA = [&](int k0) {
#pragma unroll
        for (int i = 0; i < 2; i++) {
            int idx = tid + i * 256;
            if (TA) {
                int k = idx >> 5, m4 = idx & 31;
                int gm = bm + m4 * 4;
                ra[i] = (gm < M)
                    ? *reinterpret_cast<const float4*>(Ab + (long long)(k0 + k) * M + gm)
                    : make_float4(0.f, 0.f, 0.f, 0.f);
            } else {
                int m = idx >> 2, k4 = idx & 3;
                int gm = bm + m;
                ra[i] = (gm < M)
                    ? *reinterpret_cast<const float4*>(Ab + (long long)gm * K + k0 + k4 * 4)
                    : make_float4(0.f, 0.f, 0.f, 0.f);
            }
        }
    };
    auto stA = [&](int buf) {
#pragma unroll
        for (int i = 0; i < 2; i++) {
            int idx = tid + i * 256;
            float v[4] = {ra[i].x, ra[i].y, ra[i].z, ra[i].w};
            if (TA) {
                int k = idx >> 5, m4 = idx & 31;
#pragma unroll
                for (int j = 0; j < 4; j++) As[buf][k][m4 * 4 + j] = __float_as_uint(v[j]);
            } else {
                int m = idx >> 2, k4 = idx & 3;
#pragma unroll
                for (int j = 0; j < 4; j++) As[buf][k4 * 4 + j][m] = __float_as_uint(v[j]);
            }
        }
    };
    auto ldB = [&](int k0) {
#pragma unroll
        for (int i = 0; i < 2; i++) {
            int idx = tid + i * 256;
            if (TB) {
                int n = idx >> 2, k4 = idx & 3;
                rb[i] = *reinterpret_cast<const float4*>(Bb + (long long)(bn + n) * K + k0 + k4 * 4);
            } else {
                int k = idx >> 5, n4 = idx & 31;
                rb[i] = *reinterpret_cast<const float4*>(Bb + (long long)(k0 + k) * N + bn + n4 * 4);
            }
        }
    };
    auto stB = [&](int buf) {
#pragma unroll
        for (int i = 0; i < 2; i++) {
            int idx = tid + i * 256;
            float v[4] = {rb[i].x, rb[i].y, rb[i].z, rb[i].w};
            if (TB) {
                int n = idx >> 2, k4 = idx & 3;
#pragma unroll
                for (int j = 0; j < 4; j++) Bs[buf][k4 * 4 + j][n] = __float_as_uint(v[j]);
            } else {
                int k = idx >> 5, n4 = idx & 31;
#pragma unroll
                for (int j = 0; j < 4; j++) Bs[buf][k][n4 * 4 + j] = __float_as_uint(v[j]);
            }
        }
    };
    auto compute = [&](int buf) {
#pragma unroll
        for (int ks = 0; ks < BK; ks += 8) {
            uint32_t af[4][4], bf[4][2];
#pragma unroll
            for (int mi = 0; mi < 4; mi++) {
                int mB = warpM * 64 + mi * 16;
                af[mi][0] = As[buf][ks + tig    ][mB + grp];
                af[mi][1] = As[buf][ks + tig    ][mB + grp + 8];
                af[mi][2] = As[buf][ks + tig + 4][mB + grp];
                af[mi][3] = As[buf][ks + tig + 4][mB + grp + 8];
            }
#pragma unroll
            for (int ni = 0; ni < 4; ni++) {
                int nB = warpN * 32 + ni * 8;
                bf[ni][0] = Bs[buf][ks + tig    ][nB + grp];
                bf[ni][1] = Bs[buf][ks + tig + 4][nB + grp];
            }
#pragma unroll
            for (int mi = 0; mi < 4; mi++)
#pragma unroll
                for (int ni = 0; ni < 4; ni++)
                    MMA_TF32(acc[mi][ni], af[mi], bf[ni]);
        }
    };

    const int NT = K / BK;
    ldA(0); ldB(0);
    stA(0); stB(0);
    __syncthreads();

    for (int it = 0; it < NT; ++it) {
        int buf = it & 1;
        if (it + 1 < NT) { ldA((it + 1) * BK); ldB((it + 1) * BK); }
        compute(buf);
        if (it + 1 < NT) { stA(buf ^ 1); stB(buf ^ 1); }
        __syncthreads();
    }

    // epilogue
#pragma unroll
    for (int mi = 0; mi < 4; mi++) {
#pragma unroll
        for (int half = 0; half < 2; half++) {
            int gm = bm + warpM * 64 + mi * 16 + grp + half * 8;
            if (gm >= M) continue;
            float bv = BIAS ? bias[gm] : 0.0f;
            float* crow = Cb + (long long)gm * N;
#pragma unroll
            for (int ni = 0; ni < 4; ni++) {
                int gn = bn + warpN * 32 + ni * 8 + tig * 2;
                float2 v;
                v.x = acc[mi][ni][half * 2 + 0] + bv;
                v.y = acc[mi][ni][half * 2 + 1] + bv;
                *reinterpret_cast<float2*>(&crow[gn]) = v;
            }
        }
    }
}

// ---------------- FFMA-pipe exp (x <= 0 path; ~2e-6 rel err) ----------------
// exp(x) = 2^(x*log2e); integer/frac split + degree-5 poly for 2^f, f in [-0.5,0.5].
// Avoids MUFU (rt=8/SMSP) which caps the chip at ~140G exp/s.
__device__ __forceinline__ float fexp(float x)
{
    float t  = fmaxf(x * 1.4426950408889634f, -126.0f);
    float fi = rintf(t);
    float f  = t - fi;
    float p  = 1.3333558146e-3f;
    p = fmaf(p, f, 9.6181291076e-3f);
    p = fmaf(p, f, 5.5504108665e-2f);
    p = fmaf(p, f, 2.4022650696e-1f);
    p = fmaf(p, f, 6.9314718056e-1f);
    p = fmaf(p, f, 1.0f);
    return __int_as_float(__float_as_int(p) + (((int)fi) << 23));
}

// ---------------- row softmax (in place). flip=1: softmax(rowmax - e) ----
__global__ void __launch_bounds__(256)
softmax_rows(float* __restrict__ data, int n, int flip)
{
    __shared__ float buf[4096];
    __shared__ float red[8];
    __shared__ float bcast;
    const long long row = blockIdx.x;
    float* p = data + row * (long long)n;
    const int tid = threadIdx.x;
    const int lane = tid & 31, wid = tid >> 5;

    float m = flip ? 3.0e38f : -3.0e38f;
    for (int i = tid; i < n; i += 256) {
        float v = p[i];
        buf[i] = v;
        m = flip ? fminf(m, v) : fmaxf(m, v);
    }
#pragma unroll
    for (int o = 16; o > 0; o >>= 1) {
        float t = __shfl_xor_sync(0xffffffffu, m, o);
        m = flip ? fminf(m, t) : fmaxf(m, t);
    }
    if (lane == 0) red[wid] = m;
    __syncthreads();
    if (wid == 0) {
        float v = (lane < 8) ? red[lane] : (flip ? 3.0e38f : -3.0e38f);
#pragma unroll
        for (int o = 4; o > 0; o >>= 1) {
            float t = __shfl_xor_sync(0xffffffffu, v, o);
            v = flip ? fminf(v, t) : fmaxf(v, t);
        }
        if (lane == 0) bcast = v;
    }
    __syncthreads();
    const float mx = bcast;

    float s = 0.0f;
    for (int i = tid; i < n; i += 256) {
        float e = fexp(flip ? (mx - buf[i]) : (buf[i] - mx));
        buf[i] = e;
        s += e;
    }
#pragma unroll
    for (int o = 16; o > 0; o >>= 1) s += __shfl_xor_sync(0xffffffffu, s, o);
    if (lane == 0) red[wid] = s;
    __syncthreads();
    if (wid == 0) {
        float v = (lane < 8) ? red[lane] : 0.0f;
#pragma unroll
        for (int o = 4; o > 0; o >>= 1) v += __shfl_xor_sync(0xffffffffu, v, o);
        if (lane == 0) bcast = v;
    }
    __syncthreads();
    const float inv = 1.0f / bcast;
    for (int i = tid; i < n; i += 256) p[i] = buf[i] * inv;
}

// ---------------- epilogue: out = 2x + gp*outp + gc*outc ----------------
__global__ void __launch_bounds__(256)
combine_kernel(const float4* __restrict__ x, const float4* __restrict__ op,
               const float4* __restrict__ oc, const float* __restrict__ pg,
               const float* __restrict__ cg, float4* __restrict__ out, int n4)
{
    int i = blockIdx.x * blockDim.x + threadIdx.x;
    if (i >= n4) return;
    const float a = pg[0], b = cg[0];
    float4 xv = x[i], pv = op[i], cv = oc[i];
    float4 r;
    r.x = 2.0f * xv.x + a * pv.x + b * cv.x;
    r.y = 2.0f * xv.y + a * pv.y + b * cv.y;
    r.z = 2.0f * xv.z + a * pv.z + b * cv.z;
    r.w = 2.0f * xv.w + a * pv.w + b * cv.w;
    out[i] = r;
}

// ---------------- launch ----------------
extern "C" void kernel_launch(void* const* d_in, const int* in_sizes, int n_in,
                              void* d_out, int out_size)
{
    (void)in_sizes; (void)n_in; (void)out_size;
    const float* x       = (const float*)d_in[0];
    const float* pam_wq  = (const float*)d_in[1];
    const float* pam_bq  = (const float*)d_in[2];
    const float* pam_wk  = (const float*)d_in[3];
    const float* pam_bk  = (const float*)d_in[4];
    const float* pam_wv  = (const float*)d_in[5];
    const float* pam_bv  = (const float*)d_in[6];
    const float* pam_g   = (const float*)d_in[7];
    const float* cam_wq  = (const float*)d_in[8];
    const float* cam_bq  = (const float*)d_in[9];
    const float* cam_wk  = (const float*)d_in[10];
    const float* cam_bk  = (const float*)d_in[11];
    const float* cam_wv  = (const float*)d_in[12];
    const float* cam_bv  = (const float*)d_in[13];
    const float* cam_g   = (const float*)d_in[14];

    float *qp, *kp, *vp, *qc, *kc, *vc, *attn, *ec, *outp, *outc;
    cudaGetSymbolAddress((void**)&qp,   g_qp);
    cudaGetSymbolAddress((void**)&kp,   g_kp);
    cudaGetSymbolAddress((void**)&vp,   g_vp);
    cudaGetSymbolAddress((void**)&qc,   g_qc);
    cudaGetSymbolAddress((void**)&kc,   g_kc);
    cudaGetSymbolAddress((void**)&vc,   g_vc);
    cudaGetSymbolAddress((void**)&attn, g_attn);
    cudaGetSymbolAddress((void**)&ec,   g_ec);
    cudaGetSymbolAddress((void**)&outp, g_outp);
    cudaGetSymbolAddress((void**)&outc, g_outc);

    // allow 2 CTAs/SM (2 x ~35KB smem) — raise L1 carveout to max shared
    static int carveout_done = 0;
    if (!carveout_done) {
        cudaFuncSetAttribute((const void*)gemm_tc<false,false,true>,
                             cudaFuncAttributePreferredSharedMemoryCarveout, 100);
        cudaFuncSetAttribute((const void*)gemm_tc<true,false,false>,
                             cudaFuncAttributePreferredSharedMemoryCarveout, 100);
        cudaFuncSetAttribute((const void*)gemm_tc<false,true,false>,
                             cudaFuncAttributePreferredSharedMemoryCarveout, 100);
        cudaFuncSetAttribute((const void*)gemm_tc<false,false,false>,
                             cudaFuncAttributePreferredSharedMemoryCarveout, 100);
        carveout_done = 1;
    }

    const long long xStr  = (long long)CCH * NPIX;
    const long long qStr  = (long long)C8  * NPIX;   // == 512*512
    const long long vStr  = (long long)CCH * NPIX;
    const long long aStrP = (long long)NPIX * NPIX;
    const long long eStrC = (long long)CCH * CCH;

    dim3 blk(256);

    // ---- 1. projections: C = W[M,512] * x[512,4096] + bias (NN) ----
    gemm_tc<false,false,true><<<dim3(NPIX/128, 1, BATCH), blk>>>(pam_wq, x, pam_bq, qp, C8,  NPIX, CCH, 0, xStr, qStr);
    gemm_tc<false,false,true><<<dim3(NPIX/128, 1, BATCH), blk>>>(pam_wk, x, pam_bk, kp, C8,  NPIX, CCH, 0, xStr, qStr);
    gemm_tc<false,false,true><<<dim3(NPIX/128, 4, BATCH), blk>>>(pam_wv, x, pam_bv, vp, CCH, NPIX, CCH, 0, xStr, vStr);
    gemm_tc<false,false,true><<<dim3(NPIX/128, 1, BATCH), blk>>>(cam_wq, x, cam_bq, qc, C8,  NPIX, CCH, 0, xStr, qStr);
    gemm_tc<false,false,true><<<dim3(NPIX/128, 1, BATCH), blk>>>(cam_wk, x, cam_bk, kc, C8,  NPIX, CCH, 0, xStr, qStr);
    gemm_tc<false,false,true><<<dim3(NPIX/128, 4, BATCH), blk>>>(cam_wv, x, cam_bv, vc, CCH, NPIX, CCH, 0, xStr, vStr);

    // ---- 2. PAM energy: E[q,k] = sum_d qp[d,q]*kp[d,k]  (TN, K=64) ----
    gemm_tc<true,false,false><<<dim3(NPIX/128, NPIX/128, BATCH), blk>>>(qp, kp, nullptr, attn,
        NPIX, NPIX, C8, qStr, qStr, aStrP);

    // ---- 3. PAM softmax over rows of 4096 ----
    softmax_rows<<<BATCH * NPIX, 256>>>(attn, NPIX, 0);

    // ---- 4. PAM AV: out[c,q] = sum_k vp[c,k]*attn[q,k]  (NT, K=4096) ----
    gemm_tc<false,true,false><<<dim3(NPIX/128, CCH/128, BATCH), blk>>>(vp, attn, nullptr, outp,
        CCH, NPIX, NPIX, vStr, aStrP, vStr);

    // ---- 5. CAM energy: E[i,j] = sum_m qc[i,m]*kc[j,m]  (NT, 512^3) ----
    gemm_tc<false,true,false><<<dim3(CCH/128, CCH/128, BATCH), blk>>>(qc, kc, nullptr, ec,
        CCH, CCH, CCH, qStr, qStr, eStrC);

    // ---- 6. CAM softmax of (rowmax - e) ----
    softmax_rows<<<BATCH * CCH, 256>>>(ec, CCH, 1);

    // ---- 7. CAM AV: out[c,n] = sum_d attn[c,d]*vc[d,n]  (NN) ----
    gemm_tc<false,false,false><<<dim3(NPIX/128, CCH/128, BATCH), blk>>>(ec, vc, nullptr, outc,
        CCH, NPIX, CCH, eStrC, vStr, vStr);

    // ---- 8. combine ----
    const int n4 = (BATCH * CCH * NPIX) / 4;
    combine_kernel<<<(n4 + 255) / 256, 256>>>((const float4*)x, (const float4*)outp,
        (const float4*)outc, pam_g, cam_g, (float4*)d_out, n4);
}

// round 6
// speedup vs baseline: 1.5497x; 1.5497x over previous
#include <cuda_runtime.h>
#include <cuda_bf16.h>
#include <math.h>
#include <stdint.h>

// ---------------- problem constants ----------------
#define BATCH 4
#define CCH   512
#define C8    64
#define NPIX  4096           // 64*64

// ---------------- scratch (device globals; allocation-free) ----------------
__device__ float g_qp[BATCH * C8 * NPIX];
__device__ float g_kp[BATCH * C8 * NPIX];
__device__ float g_qc[BATCH * C8 * NPIX];
__device__ float g_kc[BATCH * C8 * NPIX];
__device__ float g_energy[(size_t)BATCH * NPIX * NPIX];   // PAM energy fp32 (268MB)
__device__ float g_ec[BATCH * CCH * CCH];                 // CAM energy fp32
__device__ float g_outp[BATCH * CCH * NPIX];
__device__ float g_outc[BATCH * CCH * NPIX];
__device__ __nv_bfloat16 g_vp [BATCH * CCH * NPIX];       // PAM V, [C,N] bf16
__device__ __nv_bfloat16 g_vcT[BATCH * NPIX * CCH];       // CAM V, [N,C] bf16 (transposed)
__device__ __nv_bfloat16 g_attn[(size_t)BATCH * NPIX * NPIX]; // PAM attn bf16 (134MB)
__device__ __nv_bfloat16 g_ecb[BATCH * CCH * CCH];        // CAM attn bf16

#define MMA_TF32(acc, af, bf)                                               \
    asm volatile(                                                           \
        "mma.sync.aligned.m16n8k8.row.col.f32.tf32.tf32.f32 "               \
        "{%0,%1,%2,%3},{%4,%5,%6,%7},{%8,%9},{%0,%1,%2,%3};"                \
        : "+f"(acc[0]), "+f"(acc[1]), "+f"(acc[2]), "+f"(acc[3])            \
        : "r"(af[0]), "r"(af[1]), "r"(af[2]), "r"(af[3]),                   \
          "r"(bf[0]), "r"(bf[1]))

#define MMA_BF16(acc, af, bf)                                               \
    asm volatile(                                                           \
        "mma.sync.aligned.m16n8k16.row.col.f32.bf16.bf16.f32 "              \
        "{%0,%1,%2,%3},{%4,%5,%6,%7},{%8,%9},{%0,%1,%2,%3};"                \
        : "+f"(acc[0]), "+f"(acc[1]), "+f"(acc[2]), "+f"(acc[3])            \
        : "r"(af[0]), "r"(af[1]), "r"(af[2]), "r"(af[3]),                   \
          "r"(bf[0]), "r"(bf[1]))

// =====================================================================
// tf32 tensor-core GEMM body.  C[M,N] = A*B.
// TA: A stored [K,M]; else [M,K].  TB: B stored [N,K]; else [K,N].
// BIASR: +bias[m].  BIASC: +bias[n].  OBF: write bf16 else fp32.
// CTA tile 128x128, BK=16, 8 warps of 64x32, double-buffered smem.
// =====================================================================
template<bool TA, bool TB, bool BIASR, bool BIASC, bool OBF>
__device__ __forceinline__ void
gemm_body(const float* __restrict__ Ab, const float* __restrict__ Bb,
          const float* __restrict__ bias, void* Cb,
          int M, int N, int K, int bm, int bn)
{
    constexpr int BK = 16;
    __shared__ uint32_t As[2][BK][128 + 8];
    __shared__ uint32_t Bs[2][BK][128 + 8];

    const int tid = threadIdx.x;
    const int lane = tid & 31;
    const int grp  = lane >> 2;
    const int tig  = lane & 3;
    const int warpId = tid >> 5;
    const int warpM  = warpId >> 2;
    const int warpN  = warpId & 3;

    float acc[4][4][4];
#pragma unroll
    for (int mi = 0; mi < 4; mi++)
#pragma unroll
        for (int ni = 0; ni < 4; ni++)
#pragma unroll
            for (int r = 0; r < 4; r++) acc[mi][ni][r] = 0.0f;

    float4 ra[2], rb[2];

    auto ldA = [&](int k0) {
#pragma unroll
        for (int i = 0; i < 2; i++) {
            int idx = tid + i * 256;
            if (TA) {
                int k = idx >> 5, m4 = idx & 31;
                int gm = bm + m4 * 4;
                ra[i] = (gm < M)
                    ? *reinterpret_cast<const float4*>(Ab + (long long)(k0 + k) * M + gm)
                    : make_float4(0.f, 0.f, 0.f, 0.f);
            } else {
                int m = idx >> 2, k4 = idx & 3;
                int gm = bm + m;
                ra[i] = (gm < M)
                    ? *reinterpret_cast<const float4*>(Ab + (long long)gm * K + k0 + k4 * 4)
                    : make_float4(0.f, 0.f, 0.f, 0.f);
            }
        }
    };
    auto stA = [&](int buf) {
#pragma unroll
        for (int i = 0; i < 2; i++) {
            int idx = tid + i * 256;
            float v[4] = {ra[i].x, ra[i].y, ra[i].z, ra[i].w};
            if (TA) {
                int k = idx >> 5, m4 = idx & 31;
#pragma unroll
                for (int j = 0; j < 4; j++) As[buf][k][m4 * 4 + j] = __float_as_uint(v[j]);
            } else {
                int m = idx >> 2, k4 = idx & 3;
#pragma unroll
                for (int j = 0; j < 4; j++) As[buf][k4 * 4 + j][m] = __float_as_uint(v[j]);
            }
        }
    };
    auto ldB = [&](int k0) {
#pragma unroll
        for (int i = 0; i < 2; i++) {
            int idx = tid + i * 256;
            if (TB) {
                int n = idx >> 2, k4 = idx & 3;
                rb[i] = *reinterpret_cast<const float4*>(Bb + (long long)(bn + n) * K + k0 + k4 * 4);
            } else {
                int k = idx >> 5, n4 = idx & 31;
                rb[i] = *reinterpret_cast<const float4*>(Bb + (long long)(k0 + k) * N + bn + n4 * 4);
            }
        }
    };
    auto stB = [&](int buf) {
#pragma unroll
        for (int i = 0; i < 2; i++) {
            int idx = tid + i * 256;
            float v[4] = {rb[i].x, rb[i].y, rb[i].z, rb[i].w};
            if (TB) {
                int n = idx >> 2, k4 = idx & 3;
#pragma unroll
                for (int j = 0; j < 4; j++) Bs[buf][k4 * 4 + j][n] = __float_as_uint(v[j]);
            } else {
                int k = idx >> 5, n4 = idx & 31;
#pragma unroll
                for (int j = 0; j < 4; j++) Bs[buf][k][n4 * 4 + j] = __float_as_uint(v[j]);
            }
        }
    };
    auto compute = [&](int buf) {
#pragma unroll
        for (int ks = 0; ks < BK; ks += 8) {
            uint32_t af[4][4], bf[4][2];
#pragma unroll
            for (int mi = 0; mi < 4; mi++) {
                int mB = warpM * 64 + mi * 16;
                af[mi][0] = As[buf][ks + tig    ][mB + grp];
                af[mi][1] = As[buf][ks + tig    ][mB + grp + 8];
                af[mi][2] = As[buf][ks + tig + 4][mB + grp];
                af[mi][3] = As[buf][ks + tig + 4][mB + grp + 8];
            }
#pragma unroll
            for (int ni = 0; ni < 4; ni++) {
                int nB = warpN * 32 + ni * 8;
                bf[ni][0] = Bs[buf][ks + tig    ][nB + grp];
                bf[ni][1] = Bs[buf][ks + tig + 4][nB + grp];
            }
#pragma unroll
            for (int mi = 0; mi < 4; mi++)
#pragma unroll
                for (int ni = 0; ni < 4; ni++)
                    MMA_TF32(acc[mi][ni], af[mi], bf[ni]);
        }
    };

    const int NT = K / BK;
    ldA(0); ldB(0);
    stA(0); stB(0);
    __syncthreads();
    for (int it = 0; it < NT; ++it) {
        int buf = it & 1;
        if (it + 1 < NT) { ldA((it + 1) * BK); ldB((it + 1) * BK); }
        compute(buf);
        if (it + 1 < NT) { stA(buf ^ 1); stB(buf ^ 1); }
        __syncthreads();
    }

#pragma unroll
    for (int mi = 0; mi < 4; mi++) {
#pragma unroll
        for (int half = 0; half < 2; half++) {
            int gm = bm + warpM * 64 + mi * 16 + grp + half * 8;
            if (gm >= M) continue;
            float bv = BIASR ? bias[gm] : 0.0f;
#pragma unroll
            for (int ni = 0; ni < 4; ni++) {
                int gn = bn + warpN * 32 + ni * 8 + tig * 2;
                float vx = acc[mi][ni][half * 2 + 0] + bv;
                float vy = acc[mi][ni][half * 2 + 1] + bv;
                if (BIASC) { vx += bias[gn]; vy += bias[gn + 1]; }
                if (OBF) {
                    __nv_bfloat16* crow = (__nv_bfloat16*)Cb + (long long)gm * N;
                    *reinterpret_cast<__nv_bfloat162*>(&crow[gn]) =
                        __floats2bfloat162_rn(vx, vy);
                } else {
                    float* crow = (float*)Cb + (long long)gm * N;
                    *reinterpret_cast<float2*>(&crow[gn]) = make_float2(vx, vy);
                }
            }
        }
    }
}

// generic tf32 GEMM kernel (batched via grid.z)
template<bool TA, bool TB, bool BIASR, bool BIASC, bool OBF>
__global__ void __launch_bounds__(256, 2)
gemm_tc_k(const float* __restrict__ A, const float* __restrict__ B,
          const float* __restrict__ bias, void* C,
          int M, int N, int K,
          long long aStr, long long bStr, long long cStr)
{
    void* Cb = OBF ? (void*)((__nv_bfloat16*)C + (long long)blockIdx.z * cStr)
                   : (void*)((float*)C + (long long)blockIdx.z * cStr);
    gemm_body<TA, TB, BIASR, BIASC, OBF>(
        A + (long long)blockIdx.z * aStr, B + (long long)blockIdx.z * bStr,
        bias, Cb, M, N, K, blockIdx.y * 128, blockIdx.x * 128);
}

// 4 small projections (M=64) fused into one launch: blockIdx.y selects proj
__global__ void __launch_bounds__(256, 2)
quad_proj_k(const float* __restrict__ x,
            const float* w0, const float* b0, float* o0,
            const float* w1, const float* b1, float* o1,
            const float* w2, const float* b2, float* o2,
            const float* w3, const float* b3, float* o3)
{
    const float* W; const float* bia; float* O;
    switch (blockIdx.y) {
        case 0:  W = w0; bia = b0; O = o0; break;
        case 1:  W = w1; bia = b1; O = o1; break;
        case 2:  W = w2; bia = b2; O = o2; break;
        default: W = w3; bia = b3; O = o3; break;
    }
    const float* xb = x + (long long)blockIdx.z * (CCH * NPIX);
    float* Ob = O + (long long)blockIdx.z * (C8 * NPIX);
    gemm_body<false, false, true, false, false>(W, xb, bia, Ob,
        C8, NPIX, CCH, 0, blockIdx.x * 128);
}

// =====================================================================
// bf16 NT GEMM: C[M,N] = A[M,K] * B[N,K]^T, both bf16 row-major, fp32 out.
// CTA 128x128, 32 k per stage (16 k-pairs), m16n8k16 mma. K%32==0.
// =====================================================================
__global__ void __launch_bounds__(256, 2)
gemm_bf16_nt(const __nv_bfloat16* __restrict__ A, const __nv_bfloat16* __restrict__ B,
             float* __restrict__ C, int M, int N, int K,
             long long aStr, long long bStr, long long cStr)
{
    __shared__ uint32_t Ap[2][16][128 + 8];
    __shared__ uint32_t Bp[2][16][128 + 8];

    const __nv_bfloat16* Ab = A + (long long)blockIdx.z * aStr;
    const __nv_bfloat16* Bb = B + (long long)blockIdx.z * bStr;
    float*               Cb = C + (long long)blockIdx.z * cStr;

    const int bm = blockIdx.y * 128;
    const int bn = blockIdx.x * 128;
    const int tid = threadIdx.x;
    const int lane = tid & 31;
    const int grp  = lane >> 2;
    const int tig  = lane & 3;
    const int warpId = tid >> 5;
    const int warpM  = warpId >> 2;
    const int warpN  = warpId & 3;

    float acc[4][4][4];
#pragma unroll
    for (int mi = 0; mi < 4; mi++)
#pragma unroll
        for (int ni = 0; ni < 4; ni++)
#pragma unroll
            for (int r = 0; r < 4; r++) acc[mi][ni][r] = 0.0f;

    uint4 ra[2], rb[2];

    auto ldA = [&](int k0) {
#pragma unroll
        for (int i = 0; i < 2; i++) {
            int idx = tid + i * 256;
            int m = idx >> 2, kg = idx & 3;
            int gm = bm + m;
            ra[i] = (gm < M)
                ? *reinterpret_cast<const uint4*>(Ab + (long long)gm * K + k0 + kg * 8)
                : make_uint4(0u, 0u, 0u, 0u);
        }
    };
    auto stA = [&](int buf) {
#pragma unroll
        for (int i = 0; i < 2; i++) {
            int idx = tid + i * 256;
            int m = idx >> 2, kg = idx & 3;
            Ap[buf][kg * 4 + 0][m] = ra[i].x;
            Ap[buf][kg * 4 + 1][m] = ra[i].y;
            Ap[buf][kg * 4 + 2][m] = ra[i].z;
            Ap[buf][kg * 4 + 3][m] = ra[i].w;
        }
    };
    auto ldB = [&](int k0) {
#pragma unroll
        for (int i = 0; i < 2; i++) {
            int idx = tid + i * 256;
            int n = idx >> 2, kg = idx & 3;
            rb[i] = *reinterpret_cast<const uint4*>(Bb + (long long)(bn + n) * K + k0 + kg * 8);
        }
    };
    auto stB = [&](int buf) {
#pragma unroll
        for (int i = 0; i < 2; i++) {
            int idx = tid + i * 256;
            int n = idx >> 2, kg = idx & 3;
            Bp[buf][kg * 4 + 0][n] = rb[i].x;
            Bp[buf][kg * 4 + 1][n] = rb[i].y;
            Bp[buf][kg * 4 + 2][n] = rb[i].z;
            Bp[buf][kg * 4 + 3][n] = rb[i].w;
        }
    };
    auto compute = [&](int buf) {
#pragma unroll
        for (int c = 0; c < 2; c++) {
            const int pb = c * 8;
            uint32_t af[4][4], bf[4][2];
#pragma unroll
            for (int mi = 0; mi < 4; mi++) {
                int mB = warpM * 64 + mi * 16;
                af[mi][0] = Ap[buf][pb + tig    ][mB + grp];
                af[mi][1] = Ap[buf][pb + tig    ][mB + grp + 8];
                af[mi][2] = Ap[buf][pb + tig + 4][mB + grp];
                af[mi][3] = Ap[buf][pb + tig + 4][mB + grp + 8];
            }
#pragma unroll
            for (int ni = 0; ni < 4; ni++) {
                int nB = warpN * 32 + ni * 8;
                bf[ni][0] = Bp[buf][pb + tig    ][nB + grp];
                bf[ni][1] = Bp[buf][pb + tig + 4][nB + grp];
            }
#pragma unroll
            for (int mi = 0; mi < 4; mi++)
#pragma unroll
                for (int ni = 0; ni < 4; ni++)
                    MMA_BF16(acc[mi][ni], af[mi], bf[ni]);
        }
    };

    const int NT = K / 32;
    ldA(0); ldB(0);
    stA(0); stB(0);
    __syncthreads();
    for (int it = 0; it < NT; ++it) {
        int buf = it & 1;
        if (it + 1 < NT) { ldA((it + 1) * 32); ldB((it + 1) * 32); }
        compute(buf);
        if (it + 1 < NT) { stA(buf ^ 1); stB(buf ^ 1); }
        __syncthreads();
    }

#pragma unroll
    for (int mi = 0; mi < 4; mi++) {
#pragma unroll
        for (int half = 0; half < 2; half++) {
            int gm = bm + warpM * 64 + mi * 16 + grp + half * 8;
            if (gm >= M) continue;
            float* crow = Cb + (long long)gm * N;
#pragma unroll
            for (int ni = 0; ni < 4; ni++) {
                int gn = bn + warpN * 32 + ni * 8 + tig * 2;
                *reinterpret_cast<float2*>(&crow[gn]) =
                    make_float2(acc[mi][ni][half * 2 + 0], acc[mi][ni][half * 2 + 1]);
            }
        }
    }
}

// ---------------- FFMA-pipe exp (x <= 0 path; ~2e-6 rel err) ----------------
__device__ __forceinline__ float fexp(float x)
{
    float t  = fmaxf(x * 1.4426950408889634f, -126.0f);
    float fi = rintf(t);
    float f  = t - fi;
    float p  = 1.3333558146e-3f;
    p = fmaf(p, f, 9.6181291076e-3f);
    p = fmaf(p, f, 5.5504108665e-2f);
    p = fmaf(p, f, 2.4022650696e-1f);
    p = fmaf(p, f, 6.9314718056e-1f);
    p = fmaf(p, f, 1.0f);
    return __int_as_float(__float_as_int(p) + (((int)fi) << 23));
}

// -------- row softmax: fp32 in -> bf16 out. flip=1: softmax(rowmax - e) ----
__global__ void __launch_bounds__(256)
softmax_bf16(const float* __restrict__ in, __nv_bfloat16* __restrict__ out,
             int n, int flip)
{
    __shared__ float buf[4096];
    __shared__ float red[8];
    __shared__ float bcast;
    const long long row = blockIdx.x;
    const float* p = in + row * (long long)n;
    const int tid = threadIdx.x;
    const int lane = tid & 31, wid = tid >> 5;

    float m = flip ? 3.0e38f : -3.0e38f;
    for (int i = tid; i < n; i += 256) {
        float v = p[i];
        buf[i] = v;
        m = flip ? fminf(m, v) : fmaxf(m, v);
    }
#pragma unroll
    for (int o = 16; o > 0; o >>= 1) {
        float t = __shfl_xor_sync(0xffffffffu, m, o);
        m = flip ? fminf(m, t) : fmaxf(m, t);
    }
    if (lane == 0) red[wid] = m;
    __syncthreads();
    if (wid == 0) {
        float v = (lane < 8) ? red[lane] : (flip ? 3.0e38f : -3.0e38f);
#pragma unroll
        for (int o = 4; o > 0; o >>= 1) {
            float t = __shfl_xor_sync(0xffffffffu, v, o);
            v = flip ? fminf(v, t) : fmaxf(v, t);
        }
        if (lane == 0) bcast = v;
    }
    __syncthreads();
    const float mx = bcast;

    float s = 0.0f;
    for (int i = tid; i < n; i += 256) {
        float e = fexp(flip ? (mx - buf[i]) : (buf[i] - mx));
        buf[i] = e;
        s += e;
    }
#pragma unroll
    for (int o = 16; o > 0; o >>= 1) s += __shfl_xor_sync(0xffffffffu, s, o);
    if (lane == 0) red[wid] = s;
    __syncthreads();
    if (wid == 0) {
        float v = (lane < 8) ? red[lane] : 0.0f;
#pragma unroll
        for (int o = 4; o > 0; o >>= 1) v += __shfl_xor_sync(0xffffffffu, v, o);
        if (lane == 0) bcast = v;
    }
    __syncthreads();
    const float inv = 1.0f / bcast;
    __nv_bfloat162* o2 = reinterpret_cast<__nv_bfloat162*>(out + row * (long long)n);
    for (int i = tid * 2; i < n; i += 512)
        o2[i >> 1] = __floats2bfloat162_rn(buf[i] * inv, buf[i + 1] * inv);
}

// ---------------- epilogue: out = 2x + gp*outp + gc*outc ----------------
__global__ void __launch_bounds__(256)
combine_kernel(const float4* __restrict__ x, const float4* __restrict__ op,
               const float4* __restrict__ oc, const float* __restrict__ pg,
               const float* __restrict__ cg, float4* __restrict__ out, int n4)
{
    int i = blockIdx.x * blockDim.x + threadIdx.x;
    if (i >= n4) return;
    const float a = pg[0], b = cg[0];
    float4 xv = x[i], pv = op[i], cv = oc[i];
    float4 r;
    r.x = 2.0f * xv.x + a * pv.x + b * cv.x;
    r.y = 2.0f * xv.y + a * pv.y + b * cv.y;
    r.z = 2.0f * xv.z + a * pv.z + b * cv.z;
    r.w = 2.0f * xv.w + a * pv.w + b * cv.w;
    out[i] = r;
}

// ---------------- launch ----------------
extern "C" void kernel_launch(void* const* d_in, const int* in_sizes, int n_in,
                              void* d_out, int out_size)
{
    (void)in_sizes; (void)n_in; (void)out_size;
    const float* x       = (const float*)d_in[0];
    const float* pam_wq  = (const float*)d_in[1];
    const float* pam_bq  = (const float*)d_in[2];
    const float* pam_wk  = (const float*)d_in[3];
    const float* pam_bk  = (const float*)d_in[4];
    const float* pam_wv  = (const float*)d_in[5];
    const float* pam_bv  = (const float*)d_in[6];
    const float* pam_g   = (const float*)d_in[7];
    const float* cam_wq  = (const float*)d_in[8];
    const float* cam_bq  = (const float*)d_in[9];
    const float* cam_wk  = (const float*)d_in[10];
    const float* cam_bk  = (const float*)d_in[11];
    const float* cam_wv  = (const float*)d_in[12];
    const float* cam_bv  = (const float*)d_in[13];
    const float* cam_g   = (const float*)d_in[14];

    float *qp, *kp, *qc, *kc, *energy, *ec, *outp, *outc;
    __nv_bfloat16 *vp, *vcT, *attn, *ecb;
    cudaGetSymbolAddress((void**)&qp,     g_qp);
    cudaGetSymbolAddress((void**)&kp,     g_kp);
    cudaGetSymbolAddress((void**)&qc,     g_qc);
    cudaGetSymbolAddress((void**)&kc,     g_kc);
    cudaGetSymbolAddress((void**)&energy, g_energy);
    cudaGetSymbolAddress((void**)&ec,     g_ec);
    cudaGetSymbolAddress((void**)&outp,   g_outp);
    cudaGetSymbolAddress((void**)&outc,   g_outc);
    cudaGetSymbolAddress((void**)&vp,     g_vp);
    cudaGetSymbolAddress((void**)&vcT,    g_vcT);
    cudaGetSymbolAddress((void**)&attn,   g_attn);
    cudaGetSymbolAddress((void**)&ecb,    g_ecb);

    const long long xStr  = (long long)CCH * NPIX;
    const long long qStr  = (long long)C8  * NPIX;   // == 512*512
    const long long vStr  = (long long)CCH * NPIX;
    const long long vTStr = (long long)NPIX * CCH;
    const long long aStrP = (long long)NPIX * NPIX;
    const long long eStrC = (long long)CCH * CCH;

    dim3 blk(256);

    // ---- 1a. four small projections (q/k for PAM & CAM), one launch ----
    quad_proj_k<<<dim3(NPIX / 128, 4, BATCH), blk>>>(x,
        pam_wq, pam_bq, qp,  pam_wk, pam_bk, kp,
        cam_wq, cam_bq, qc,  cam_wk, cam_bk, kc);

    // ---- 1b. PAM V projection -> bf16 [C, N] ----
    gemm_tc_k<false, false, true, false, true><<<dim3(NPIX / 128, CCH / 128, BATCH), blk>>>(
        pam_wv, x, pam_bv, vp, CCH, NPIX, CCH, 0, xStr, vStr);

    // ---- 1c. CAM V projection, transposed output -> bf16 [N, C] ----
    //   vcT[n, c] = sum_k x[k, n] * W[c, k] + b[c]   (TA: x is [K,M]; TB: W is [N,K])
    gemm_tc_k<true, true, false, true, true><<<dim3(CCH / 128, NPIX / 128, BATCH), blk>>>(
        x, cam_wv, cam_bv, vcT, NPIX, CCH, CCH, xStr, 0, vTStr);

    // ---- 2. PAM energy: E[q,k] = sum_d qp[d,q]*kp[d,k]  (TN, K=64, fp32 out) ----
    gemm_tc_k<true, false, false, false, false><<<dim3(NPIX / 128, NPIX / 128, BATCH), blk>>>(
        qp, kp, nullptr, energy, NPIX, NPIX, C8, qStr, qStr, aStrP);

    // ---- 3. PAM softmax: fp32 energy -> bf16 attn ----
    softmax_bf16<<<BATCH * NPIX, 256>>>(energy, attn, NPIX, 0);

    // ---- 4. PAM AV (bf16 NT): out[c,q] = sum_k vp[c,k] * attn[q,k] ----
    gemm_bf16_nt<<<dim3(NPIX / 128, CCH / 128, BATCH), blk>>>(
        vp, attn, outp, CCH, NPIX, NPIX, vStr, aStrP, vStr);

    // ---- 5. CAM energy: E[i,j] = sum_m qc[i,m]*kc[j,m]  (NT tf32, fp32 out) ----
    gemm_tc_k<false, true, false, false, false><<<dim3(CCH / 128, CCH / 128, BATCH), blk>>>(
        qc, kc, nullptr, ec, CCH, CCH, CCH, qStr, qStr, eStrC);

    // ---- 6. CAM softmax (flipped) -> bf16 ----
    softmax_bf16<<<BATCH * CCH, 256>>>(ec, ecb, CCH, 1);

    // ---- 7. CAM AV (bf16 NT): out[c,n] = sum_d ecb[c,d] * vcT[n,d] ----
    gemm_bf16_nt<<<dim3(NPIX / 128, CCH / 128, BATCH), blk>>>(
        ecb, vcT, outc, CCH, NPIX, CCH, eStrC, vTStr, vStr);

    // ---- 8. combine ----
    const int n4 = (BATCH * CCH * NPIX) / 4;
    combine_kernel<<<(n4 + 255) / 256, 256>>>((const float4*)x, (const float4*)outp,
        (const float4*)outc, pam_g, cam_g, (float4*)d_out, n4);
}

// round 7
// speedup vs baseline: 1.5594x; 1.0063x over previous
#include <cuda_runtime.h>
#include <cuda_bf16.h>
#include <math.h>
#include <stdint.h>

// ---------------- problem constants ----------------
#define BATCH 4
#define CCH   512
#define C8    64
#define NPIX  4096           // 64*64
#define NKT   32             // key tiles of 128 in PAM

// ---------------- scratch (device globals; allocation-free) ----------------
__device__ float g_qp[BATCH * C8 * NPIX];
__device__ float g_kp[BATCH * C8 * NPIX];
__device__ float g_qc[BATCH * C8 * NPIX];
__device__ float g_kc[BATCH * C8 * NPIX];
__device__ float g_energy[(size_t)BATCH * NPIX * NPIX];   // PAM energy fp32 (268MB)
__device__ float g_maxp[BATCH * NKT * NPIX];              // per-(ktile) row maxima
__device__ float g_ec[BATCH * CCH * CCH];                 // CAM energy fp32
__device__ float g_outp[BATCH * CCH * NPIX];
__device__ float g_outc[BATCH * CCH * NPIX];
__device__ __nv_bfloat16 g_vp [BATCH * CCH * NPIX];       // PAM V, [C,N] bf16
__device__ __nv_bfloat16 g_vcT[BATCH * NPIX * CCH];       // CAM V, [N,C] bf16
__device__ __nv_bfloat16 g_ecb[BATCH * CCH * CCH];        // CAM attn bf16

#define MMA_TF32(acc, af, bf)                                               \
    asm volatile(                                                           \
        "mma.sync.aligned.m16n8k8.row.col.f32.tf32.tf32.f32 "               \
        "{%0,%1,%2,%3},{%4,%5,%6,%7},{%8,%9},{%0,%1,%2,%3};"                \
        : "+f"(acc[0]), "+f"(acc[1]), "+f"(acc[2]), "+f"(acc[3])            \
        : "r"(af[0]), "r"(af[1]), "r"(af[2]), "r"(af[3]),                   \
          "r"(bf[0]), "r"(bf[1]))

#define MMA_BF16(acc, af, bf)                                               \
    asm volatile(                                                           \
        "mma.sync.aligned.m16n8k16.row.col.f32.bf16.bf16.f32 "              \
        "{%0,%1,%2,%3},{%4,%5,%6,%7},{%8,%9},{%0,%1,%2,%3};"                \
        : "+f"(acc[0]), "+f"(acc[1]), "+f"(acc[2]), "+f"(acc[3])            \
        : "r"(af[0]), "r"(af[1]), "r"(af[2]), "r"(af[3]),                   \
          "r"(bf[0]), "r"(bf[1]))

// ---------------- FFMA-pipe exp (x <= 0 path; ~2e-6 rel err) ----------------
__device__ __forceinline__ float fexp(float x)
{
    float t  = fmaxf(x * 1.4426950408889634f, -126.0f);
    float fi = rintf(t);
    float f  = t - fi;
    float p  = 1.3333558146e-3f;
    p = fmaf(p, f, 9.6181291076e-3f);
    p = fmaf(p, f, 5.5504108665e-2f);
    p = fmaf(p, f, 2.4022650696e-1f);
    p = fmaf(p, f, 6.9314718056e-1f);
    p = fmaf(p, f, 1.0f);
    return __int_as_float(__float_as_int(p) + (((int)fi) << 23));
}

// =====================================================================
// tf32 tensor-core GEMM body.  C[M,N] = A*B.
// TA: A stored [K,M]; else [M,K].  TB: B stored [N,K]; else [K,N].
// BIASR: +bias[m].  BIASC: +bias[n].  OBF: write bf16 else fp32.
// WMAX: also write per-row (M) maxima of this CTA's tile to gmaxRow[0..127].
// =====================================================================
template<bool TA, bool TB, bool BIASR, bool BIASC, bool OBF, bool WMAX = false>
__device__ __forceinline__ void
gemm_body(const float* __restrict__ Ab, const float* __restrict__ Bb,
          const float* __restrict__ bias, void* Cb,
          int M, int N, int K, int bm, int bn, float* gmaxRow)
{
    constexpr int BK = 16;
    __shared__ uint32_t As[2][BK][128 + 8];
    __shared__ uint32_t Bs[2][BK][128 + 8];
    __shared__ float smx[WMAX ? 4 : 1][WMAX ? 128 : 1];

    const int tid = threadIdx.x;
    const int lane = tid & 31;
    const int grp  = lane >> 2;
    const int tig  = lane & 3;
    const int warpId = tid >> 5;
    const int warpM  = warpId >> 2;
    const int warpN  = warpId & 3;

    float acc[4][4][4];
#pragma unroll
    for (int mi = 0; mi < 4; mi++)
#pragma unroll
        for (int ni = 0; ni < 4; ni++)
#pragma unroll
            for (int r = 0; r < 4; r++) acc[mi][ni][r] = 0.0f;

    float4 ra[2], rb[2];

    auto ldA = [&](int k0) {
#pragma unroll
        for (int i = 0; i < 2; i++) {
            int idx = tid + i * 256;
            if (TA) {
                int k = idx >> 5, m4 = idx & 31;
                int gm = bm + m4 * 4;
                ra[i] = (gm < M)
                    ? *reinterpret_cast<const float4*>(Ab + (long long)(k0 + k) * M + gm)
                    : make_float4(0.f, 0.f, 0.f, 0.f);
            } else {
                int m = idx >> 2, k4 = idx & 3;
                int gm = bm + m;
                ra[i] = (gm < M)
                    ? *reinterpret_cast<const float4*>(Ab + (long long)gm * K + k0 + k4 * 4)
                    : make_float4(0.f, 0.f, 0.f, 0.f);
            }
        }
    };
    auto stA = [&](int buf) {
#pragma unroll
        for (int i = 0; i < 2; i++) {
            int idx = tid + i * 256;
            float v[4] = {ra[i].x, ra[i].y, ra[i].z, ra[i].w};
            if (TA) {
                int k = idx >> 5, m4 = idx & 31;
#pragma unroll
                for (int j = 0; j < 4; j++) As[buf][k][m4 * 4 + j] = __float_as_uint(v[j]);
            } else {
                int m = idx >> 2, k4 = idx & 3;
#pragma unroll
                for (int j = 0; j < 4; j++) As[buf][k4 * 4 + j][m] = __float_as_uint(v[j]);
            }
        }
    };
    auto ldB = [&](int k0) {
#pragma unroll
        for (int i = 0; i < 2; i++) {
            int idx = tid + i * 256;
            if (TB) {
                int n = idx >> 2, k4 = idx & 3;
                rb[i] = *reinterpret_cast<const float4*>(Bb + (long long)(bn + n) * K + k0 + k4 * 4);
            } else {
                int k = idx >> 5, n4 = idx & 31;
                rb[i] = *reinterpret_cast<const float4*>(Bb + (long long)(k0 + k) * N + bn + n4 * 4);
            }
        }
    };
    auto stB = [&](int buf) {
#pragma unroll
        for (int i = 0; i < 2; i++) {
            int idx = tid + i * 256;
            float v[4] = {rb[i].x, rb[i].y, rb[i].z, rb[i].w};
            if (TB) {
                int n = idx >> 2, k4 = idx & 3;
#pragma unroll
                for (int j = 0; j < 4; j++) Bs[buf][k4 * 4 + j][n] = __float_as_uint(v[j]);
            } else {
                int k = idx >> 5, n4 = idx & 31;
#pragma unroll
                for (int j = 0; j < 4; j++) Bs[buf][k][n4 * 4 + j] = __float_as_uint(v[j]);
            }
        }
    };
    auto compute = [&](int buf) {
#pragma unroll
        for (int ks = 0; ks < BK; ks += 8) {
            uint32_t af[4][4], bf[4][2];
#pragma unroll
            for (int mi = 0; mi < 4; mi++) {
                int mB = warpM * 64 + mi * 16;
                af[mi][0] = As[buf][ks + tig    ][mB + grp];
                af[mi][1] = As[buf][ks + tig    ][mB + grp + 8];
                af[mi][2] = As[buf][ks + tig + 4][mB + grp];
                af[mi][3] = As[buf][ks + tig + 4][mB + grp + 8];
            }
#pragma unroll
            for (int ni = 0; ni < 4; ni++) {
                int nB = warpN * 32 + ni * 8;
                bf[ni][0] = Bs[buf][ks + tig    ][nB + grp];
                bf[ni][1] = Bs[buf][ks + tig + 4][nB + grp];
            }
#pragma unroll
            for (int mi = 0; mi < 4; mi++)
#pragma unroll
                for (int ni = 0; ni < 4; ni++)
                    MMA_TF32(acc[mi][ni], af[mi], bf[ni]);
        }
    };

    const int NT = K / BK;
    ldA(0); ldB(0);
    stA(0); stB(0);
    __syncthreads();
    for (int it = 0; it < NT; ++it) {
        int buf = it & 1;
        if (it + 1 < NT) { ldA((it + 1) * BK); ldB((it + 1) * BK); }
        compute(buf);
        if (it + 1 < NT) { stA(buf ^ 1); stB(buf ^ 1); }
        __syncthreads();
    }

    if (WMAX) {
        // per-row maxima of the 128x128 tile
#pragma unroll
        for (int mi = 0; mi < 4; mi++) {
#pragma unroll
            for (int half = 0; half < 2; half++) {
                float rm = -3.0e38f;
#pragma unroll
                for (int ni = 0; ni < 4; ni++)
                    rm = fmaxf(rm, fmaxf(acc[mi][ni][half * 2], acc[mi][ni][half * 2 + 1]));
                rm = fmaxf(rm, __shfl_xor_sync(0xffffffffu, rm, 1));
                rm = fmaxf(rm, __shfl_xor_sync(0xffffffffu, rm, 2));
                if (tig == 0) smx[warpN][warpM * 64 + mi * 16 + grp + half * 8] = rm;
            }
        }
        __syncthreads();
        if (tid < 128)
            gmaxRow[tid] = fmaxf(fmaxf(smx[0][tid], smx[1][tid]),
                                 fmaxf(smx[2][tid], smx[3][tid]));
    }

#pragma unroll
    for (int mi = 0; mi < 4; mi++) {
#pragma unroll
        for (int half = 0; half < 2; half++) {
            int gm = bm + warpM * 64 + mi * 16 + grp + half * 8;
            if (gm >= M) continue;
            float bv = BIASR ? bias[gm] : 0.0f;
#pragma unroll
            for (int ni = 0; ni < 4; ni++) {
                int gn = bn + warpN * 32 + ni * 8 + tig * 2;
                float vx = acc[mi][ni][half * 2 + 0] + bv;
                float vy = acc[mi][ni][half * 2 + 1] + bv;
                if (BIASC) { vx += bias[gn]; vy += bias[gn + 1]; }
                if (OBF) {
                    __nv_bfloat16* crow = (__nv_bfloat16*)Cb + (long long)gm * N;
                    *reinterpret_cast<__nv_bfloat162*>(&crow[gn]) =
                        __floats2bfloat162_rn(vx, vy);
                } else {
                    float* crow = (float*)Cb + (long long)gm * N;
                    *reinterpret_cast<float2*>(&crow[gn]) = make_float2(vx, vy);
                }
            }
        }
    }
}

// generic tf32 GEMM kernel (batched via grid.z)
template<bool TA, bool TB, bool BIASR, bool BIASC, bool OBF>
__global__ void __launch_bounds__(256, 2)
gemm_tc_k(const float* __restrict__ A, const float* __restrict__ B,
          const float* __restrict__ bias, void* C,
          int M, int N, int K,
          long long aStr, long long bStr, long long cStr)
{
    void* Cb = OBF ? (void*)((__nv_bfloat16*)C + (long long)blockIdx.z * cStr)
                   : (void*)((float*)C + (long long)blockIdx.z * cStr);
    gemm_body<TA, TB, BIASR, BIASC, OBF>(
        A + (long long)blockIdx.z * aStr, B + (long long)blockIdx.z * bStr,
        bias, Cb, M, N, K, blockIdx.y * 128, blockIdx.x * 128, nullptr);
}

// PAM energy: E[q,k] = sum_d qp[d,q]*kp[d,k]  (TN, K=64) + per-tile row maxima
__global__ void __launch_bounds__(256, 2)
pam_energy_k(const float* __restrict__ qp, const float* __restrict__ kp,
             float* __restrict__ energy, float* __restrict__ gmax)
{
    const long long qStr = (long long)C8 * NPIX;
    const long long aStr = (long long)NPIX * NPIX;
    float* gmaxRow = gmax + ((long long)blockIdx.z * NKT + blockIdx.x) * NPIX
                          + blockIdx.y * 128;
    gemm_body<true, false, false, false, false, true>(
        qp + (long long)blockIdx.z * qStr, kp + (long long)blockIdx.z * qStr,
        nullptr, energy + (long long)blockIdx.z * aStr,
        NPIX, NPIX, C8, blockIdx.y * 128, blockIdx.x * 128, gmaxRow);
}

// 4 small projections (M=64) fused into one launch: blockIdx.y selects proj
__global__ void __launch_bounds__(256, 2)
quad_proj_k(const float* __restrict__ x,
            const float* w0, const float* b0, float* o0,
            const float* w1, const float* b1, float* o1,
            const float* w2, const float* b2, float* o2,
            const float* w3, const float* b3, float* o3)
{
    const float* W; const float* bia; float* O;
    switch (blockIdx.y) {
        case 0:  W = w0; bia = b0; O = o0; break;
        case 1:  W = w1; bia = b1; O = o1; break;
        case 2:  W = w2; bia = b2; O = o2; break;
        default: W = w3; bia = b3; O = o3; break;
    }
    const float* xb = x + (long long)blockIdx.z * (CCH * NPIX);
    float* Ob = O + (long long)blockIdx.z * (C8 * NPIX);
    gemm_body<false, false, true, false, false>(W, xb, bia, Ob,
        C8, NPIX, CCH, 0, blockIdx.x * 128, nullptr);
}

// =====================================================================
// bf16 NT GEMM: C[M,N] = A[M,K] * B[N,K]^T, fp32 out.
// EXPB: B source is RAW fp32 energy; converts p=exp(s-m[row]) to bf16 on
// the fly, accumulates row sums l, and scales output columns by 1/l.
// CTA 128x128, 32 k per stage, m16n8k16 mma. K%32==0.
// =====================================================================
template<bool EXPB>
__global__ void __launch_bounds__(256, 2)
gemm_bf16_nt(const __nv_bfloat16* __restrict__ A, const void* __restrict__ Bv,
             float* __restrict__ C, const float* __restrict__ gmax,
             int M, int N, int K,
             long long aStr, long long bStr, long long cStr)
{
    __shared__ uint32_t Ap[2][16][128 + 8];
    __shared__ uint32_t Bp[2][16][128 + 8];
    __shared__ float sm_m[EXPB ? 128 : 1];
    __shared__ float sm_l[EXPB ? 128 : 1];

    const __nv_bfloat16* Ab = A + (long long)blockIdx.z * aStr;
    const __nv_bfloat16* Bb_h = EXPB ? nullptr
        : (const __nv_bfloat16*)Bv + (long long)blockIdx.z * bStr;
    const float* Bb_f = EXPB
        ? (const float*)Bv + (long long)blockIdx.z * bStr : nullptr;
    float* Cb = C + (long long)blockIdx.z * cStr;

    const int bm = blockIdx.y * 128;
    const int bn = blockIdx.x * 128;
    const int tid = threadIdx.x;
    const int lane = tid & 31;
    const int grp  = lane >> 2;
    const int tig  = lane & 3;
    const int warpId = tid >> 5;
    const int warpM  = warpId >> 2;
    const int warpN  = warpId & 3;

    float m0 = 0.f, m1 = 0.f, lsum0 = 0.f, lsum1 = 0.f;
    if (EXPB) {
        if (tid < 128) {
            const float* gb = gmax + (long long)blockIdx.z * NKT * NPIX + bn + tid;
            float mx = -3.0e38f;
#pragma unroll
            for (int kt = 0; kt < NKT; kt++) mx = fmaxf(mx, gb[kt * NPIX]);
            sm_m[tid] = mx;
        }
        __syncthreads();
        m0 = sm_m[tid >> 2];
        m1 = sm_m[64 + (tid >> 2)];
    }

    float acc[4][4][4];
#pragma unroll
    for (int mi = 0; mi < 4; mi++)
#pragma unroll
        for (int ni = 0; ni < 4; ni++)
#pragma unroll
            for (int r = 0; r < 4; r++) acc[mi][ni][r] = 0.0f;

    uint4 ra[2], rb[2];
    float4 rbf[2][2];

    auto ldA = [&](int k0) {
#pragma unroll
        for (int i = 0; i < 2; i++) {
            int idx = tid + i * 256;
            int m = idx >> 2, kg = idx & 3;
            int gm = bm + m;
            ra[i] = (gm < M)
                ? *reinterpret_cast<const uint4*>(Ab + (long long)gm * K + k0 + kg * 8)
                : make_uint4(0u, 0u, 0u, 0u);
        }
    };
    auto stA = [&](int buf) {
#pragma unroll
        for (int i = 0; i < 2; i++) {
            int idx = tid + i * 256;
            int m = idx >> 2, kg = idx & 3;
            Ap[buf][kg * 4 + 0][m] = ra[i].x;
            Ap[buf][kg * 4 + 1][m] = ra[i].y;
            Ap[buf][kg * 4 + 2][m] = ra[i].z;
            Ap[buf][kg * 4 + 3][m] = ra[i].w;
        }
    };
    auto ldB = [&](int k0) {
#pragma unroll
        for (int i = 0; i < 2; i++) {
            int idx = tid + i * 256;
            int n = idx >> 2, kg = idx & 3;
            if (EXPB) {
                const float* src = Bb_f + (long long)(bn + n) * K + k0 + kg * 8;
                rbf[i][0] = *reinterpret_cast<const float4*>(src);
                rbf[i][1] = *reinterpret_cast<const float4*>(src + 4);
            } else {
                rb[i] = *reinterpret_cast<const uint4*>(Bb_h + (long long)(bn + n) * K + k0 + kg * 8);
            }
        }
    };
    auto stB = [&](int buf) {
#pragma unroll
        for (int i = 0; i < 2; i++) {
            int idx = tid + i * 256;
            int n = idx >> 2, kg = idx & 3;
            if (EXPB) {
                float mrow = i ? m1 : m0;
                float s[8] = {rbf[i][0].x, rbf[i][0].y, rbf[i][0].z, rbf[i][0].w,
                              rbf[i][1].x, rbf[i][1].y, rbf[i][1].z, rbf[i][1].w};
                float p[8];
                float ls = 0.f;
#pragma unroll
                for (int j = 0; j < 8; j++) { p[j] = fexp(s[j] - mrow); ls += p[j]; }
                if (i) lsum1 += ls; else lsum0 += ls;
#pragma unroll
                for (int j = 0; j < 4; j++) {
                    __nv_bfloat162 h = __floats2bfloat162_rn(p[2 * j], p[2 * j + 1]);
                    Bp[buf][kg * 4 + j][n] = *reinterpret_cast<uint32_t*>(&h);
                }
            } else {
                Bp[buf][kg * 4 + 0][n] = rb[i].x;
                Bp[buf][kg * 4 + 1][n] = rb[i].y;
                Bp[buf][kg * 4 + 2][n] = rb[i].z;
                Bp[buf][kg * 4 + 3][n] = rb[i].w;
            }
        }
    };
    auto compute = [&](int buf) {
#pragma unroll
        for (int c = 0; c < 2; c++) {
            const int pb = c * 8;
            uint32_t af[4][4], bf[4][2];
#pragma unroll
            for (int mi = 0; mi < 4; mi++) {
                int mB = warpM * 64 + mi * 16;
                af[mi][0] = Ap[buf][pb + tig    ][mB + grp];
                af[mi][1] = Ap[buf][pb + tig    ][mB + grp + 8];
                af[mi][2] = Ap[buf][pb + tig + 4][mB + grp];
                af[mi][3] = Ap[buf][pb + tig + 4][mB + grp + 8];
            }
#pragma unroll
            for (int ni = 0; ni < 4; ni++) {
                int nB = warpN * 32 + ni * 8;
                bf[ni][0] = Bp[buf][pb + tig    ][nB + grp];
                bf[ni][1] = Bp[buf][pb + tig + 4][nB + grp];
            }
#pragma unroll
            for (int mi = 0; mi < 4; mi++)
#pragma unroll
                for (int ni = 0; ni < 4; ni++)
                    MMA_BF16(acc[mi][ni], af[mi], bf[ni]);
        }
    };

    const int NT = K / 32;
    ldA(0); ldB(0);
    stA(0); stB(0);
    __syncthreads();
    for (int it = 0; it < NT; ++it) {
        int buf = it & 1;
        if (it + 1 < NT) { ldA((it + 1) * 32); ldB((it + 1) * 32); }
        compute(buf);
        if (it + 1 < NT) { stA(buf ^ 1); stB(buf ^ 1); }
        __syncthreads();
    }

    if (EXPB) {
        // reduce row sums across the 4 loader lanes of each row, invert
        lsum0 += __shfl_xor_sync(0xffffffffu, lsum0, 1);
        lsum0 += __shfl_xor_sync(0xffffffffu, lsum0, 2);
        lsum1 += __shfl_xor_sync(0xffffffffu, lsum1, 1);
        lsum1 += __shfl_xor_sync(0xffffffffu, lsum1, 2);
        if ((tid & 3) == 0) {
            sm_l[tid >> 2] = lsum0;
            sm_l[64 + (tid >> 2)] = lsum1;
        }
        __syncthreads();
        if (tid < 128) sm_l[tid] = 1.0f / sm_l[tid];
        __syncthreads();
    }

#pragma unroll
    for (int mi = 0; mi < 4; mi++) {
#pragma unroll
        for (int half = 0; half < 2; half++) {
            int gm = bm + warpM * 64 + mi * 16 + grp + half * 8;
            if (gm >= M) continue;
            float* crow = Cb + (long long)gm * N;
#pragma unroll
            for (int ni = 0; ni < 4; ni++) {
                int gn = bn + warpN * 32 + ni * 8 + tig * 2;
                float vx = acc[mi][ni][half * 2 + 0];
                float vy = acc[mi][ni][half * 2 + 1];
                if (EXPB) {
                    vx *= sm_l[gn - bn];
                    vy *= sm_l[gn - bn + 1];
                }
                *reinterpret_cast<float2*>(&crow[gn]) = make_float2(vx, vy);
            }
        }
    }
}

// -------- row softmax: fp32 in -> bf16 out. flip=1: softmax(rowmax - e) ----
__global__ void __launch_bounds__(256)
softmax_bf16(const float* __restrict__ in, __nv_bfloat16* __restrict__ out,
             int n, int flip)
{
    __shared__ float buf[4096];
    __shared__ float red[8];
    __shared__ float bcast;
    const long long row = blockIdx.x;
    const float* p = in + row * (long long)n;
    const int tid = threadIdx.x;
    const int lane = tid & 31, wid = tid >> 5;

    float m = flip ? 3.0e38f : -3.0e38f;
    for (int i = tid; i < n; i += 256) {
        float v = p[i];
        buf[i] = v;
        m = flip ? fminf(m, v) : fmaxf(m, v);
    }
#pragma unroll
    for (int o = 16; o > 0; o >>= 1) {
        float t = __shfl_xor_sync(0xffffffffu, m, o);
        m = flip ? fminf(m, t) : fmaxf(m, t);
    }
    if (lane == 0) red[wid] = m;
    __syncthreads();
    if (wid == 0) {
        float v = (lane < 8) ? red[lane] : (flip ? 3.0e38f : -3.0e38f);
#pragma unroll
        for (int o = 4; o > 0; o >>= 1) {
            float t = __shfl_xor_sync(0xffffffffu, v, o);
            v = flip ? fminf(v, t) : fmaxf(v, t);
        }
        if (lane == 0) bcast = v;
    }
    __syncthreads();
    const float mx = bcast;

    float s = 0.0f;
    for (int i = tid; i < n; i += 256) {
        float e = fexp(flip ? (mx - buf[i]) : (buf[i] - mx));
        buf[i] = e;
        s += e;
    }
#pragma unroll
    for (int o = 16; o > 0; o >>= 1) s += __shfl_xor_sync(0xffffffffu, s, o);
    if (lane == 0) red[wid] = s;
    __syncthreads();
    if (wid == 0) {
        float v = (lane < 8) ? red[lane] : 0.0f;
#pragma unroll
        for (int o = 4; o > 0; o >>= 1) v += __shfl_xor_sync(0xffffffffu, v, o);
        if (lane == 0) bcast = v;
    }
    __syncthreads();
    const float inv = 1.0f / bcast;
    __nv_bfloat162* o2 = reinterpret_cast<__nv_bfloat162*>(out + row * (long long)n);
    for (int i = tid * 2; i < n; i += 512)
        o2[i >> 1] = __floats2bfloat162_rn(buf[i] * inv, buf[i + 1] * inv);
}

// ---------------- epilogue: out = 2x + gp*outp + gc*outc ----------------
__global__ void __launch_bounds__(256)
combine_kernel(const float4* __restrict__ x, const float4* __restrict__ op,
               const float4* __restrict__ oc, const float* __restrict__ pg,
               const float* __restrict__ cg, float4* __restrict__ out, int n4)
{
    int i = blockIdx.x * blockDim.x + threadIdx.x;
    if (i >= n4) return;
    const float a = pg[0], b = cg[0];
    float4 xv = x[i], pv = op[i], cv = oc[i];
    float4 r;
    r.x = 2.0f * xv.x + a * pv.x + b * cv.x;
    r.y = 2.0f * xv.y + a * pv.y + b * cv.y;
    r.z = 2.0f * xv.z + a * pv.z + b * cv.z;
    r.w = 2.0f * xv.w + a * pv.w + b * cv.w;
    out[i] = r;
}

// ---------------- launch ----------------
extern "C" void kernel_launch(void* const* d_in, const int* in_sizes, int n_in,
                              void* d_out, int out_size)
{
    (void)in_sizes; (void)n_in; (void)out_size;
    const float* x       = (const float*)d_in[0];
    const float* pam_wq  = (const float*)d_in[1];
    const float* pam_bq  = (const float*)d_in[2];
    const float* pam_wk  = (const float*)d_in[3];
    const float* pam_bk  = (const float*)d_in[4];
    const float* pam_wv  = (const float*)d_in[5];
    const float* pam_bv  = (const float*)d_in[6];
    const float* pam_g   = (const float*)d_in[7];
    const float* cam_wq  = (const float*)d_in[8];
    const float* cam_bq  = (const float*)d_in[9];
    const float* cam_wk  = (const float*)d_in[10];
    const float* cam_bk  = (const float*)d_in[11];
    const float* cam_wv  = (const float*)d_in[12];
    const float* cam_bv  = (const float*)d_in[13];
    const float* cam_g   = (const float*)d_in[14];

    float *qp, *kp, *qc, *kc, *energy, *gmax, *ec, *outp, *outc;
    __nv_bfloat16 *vp, *vcT, *ecb;
    cudaGetSymbolAddress((void**)&qp,     g_qp);
    cudaGetSymbolAddress((void**)&kp,     g_kp);
    cudaGetSymbolAddress((void**)&qc,     g_qc);
    cudaGetSymbolAddress((void**)&kc,     g_kc);
    cudaGetSymbolAddress((void**)&energy, g_energy);
    cudaGetSymbolAddress((void**)&gmax,   g_maxp);
    cudaGetSymbolAddress((void**)&ec,     g_ec);
    cudaGetSymbolAddress((void**)&outp,   g_outp);
    cudaGetSymbolAddress((void**)&outc,   g_outc);
    cudaGetSymbolAddress((void**)&vp,     g_vp);
    cudaGetSymbolAddress((void**)&vcT,    g_vcT);
    cudaGetSymbolAddress((void**)&ecb,    g_ecb);

    const long long xStr  = (long long)CCH * NPIX;
    const long long vStr  = (long long)CCH * NPIX;
    const long long vTStr = (long long)NPIX * CCH;
    const long long aStrP = (long long)NPIX * NPIX;
    const long long eStrC = (long long)CCH * CCH;
    const long long qStr  = (long long)C8 * NPIX;

    dim3 blk(256);

    // ---- 1a. four small projections (q/k for PAM & CAM), one launch ----
    quad_proj_k<<<dim3(NPIX / 128, 4, BATCH), blk>>>(x,
        pam_wq, pam_bq, qp,  pam_wk, pam_bk, kp,
        cam_wq, cam_bq, qc,  cam_wk, cam_bk, kc);

    // ---- 1b. PAM V projection -> bf16 [C, N] ----
    gemm_tc_k<false, false, true, false, true><<<dim3(NPIX / 128, CCH / 128, BATCH), blk>>>(
        pam_wv, x, pam_bv, vp, CCH, NPIX, CCH, 0, xStr, vStr);

    // ---- 1c. CAM V projection, transposed output -> bf16 [N, C] ----
    gemm_tc_k<true, true, false, true, true><<<dim3(CCH / 128, NPIX / 128, BATCH), blk>>>(
        x, cam_wv, cam_bv, vcT, NPIX, CCH, CCH, xStr, 0, vTStr);

    // ---- 2. PAM energy (fp32) + per-tile row maxima ----
    pam_energy_k<<<dim3(NPIX / 128, NPIX / 128, BATCH), blk>>>(qp, kp, energy, gmax);

    // ---- 3. PAM AV with fused exp/normalize:
    //         out[c,q] = sum_k vp[c,k] * exp(E[q,k]-m[q]) / l[q] ----
    gemm_bf16_nt<true><<<dim3(NPIX / 128, CCH / 128, BATCH), blk>>>(
        vp, energy, outp, gmax, CCH, NPIX, NPIX, vStr, aStrP, vStr);

    // ---- 4. CAM energy (NT tf32, fp32 out) ----
    gemm_tc_k<false, true, false, false, false><<<dim3(CCH / 128, CCH / 128, BATCH), blk>>>(
        qc, kc, nullptr, ec, CCH, CCH, CCH, qStr, qStr, eStrC);

    // ---- 5. CAM softmax (flipped) -> bf16 ----
    softmax_bf16<<<BATCH * CCH, 256>>>(ec, ecb, CCH, 1);

    // ---- 6. CAM AV (bf16 NT): out[c,n] = sum_d ecb[c,d] * vcT[n,d] ----
    gemm_bf16_nt<false><<<dim3(NPIX / 128, CCH / 128, BATCH), blk>>>(
        ecb, vcT, outc, nullptr, CCH, NPIX, CCH, eStrC, vTStr, vStr);

    // ---- 7. combine ----
    const int n4 = (BATCH * CCH * NPIX) / 4;
    combine_kernel<<<(n4 + 255) / 256, 256>>>((const float4*)x, (const float4*)outp,
        (const float4*)outc, pam_g, cam_g, (float4*)d_out, n4);
}

// round 8
// speedup vs baseline: 1.6973x; 1.0884x over previous
#include <cuda_runtime.h>
#include <cuda_bf16.h>
#include <cuda_fp16.h>
#include <math.h>
#include <stdint.h>

// ---------------- problem constants ----------------
#define BATCH 4
#define CCH   512
#define C8    64
#define NPIX  4096           // 64*64
#define NKT   32             // key tiles of 128 in PAM

// ---------------- scratch (device globals; allocation-free) ----------------
__device__ float g_qp[BATCH * C8 * NPIX];
__device__ float g_kp[BATCH * C8 * NPIX];
__device__ float g_qc[BATCH * C8 * NPIX];
__device__ float g_kc[BATCH * C8 * NPIX];
__device__ float g_maxp[BATCH * NKT * NPIX];              // per-tile row maxima
__device__ float g_sump[BATCH * NKT * NPIX];              // per-tile row sums of p~
__device__ float g_ec[BATCH * CCH * CCH];                 // CAM energy fp32
__device__ float g_outp[BATCH * CCH * NPIX];              // PAM out (pre-gamma)
__device__ __nv_bfloat16 g_vp [BATCH * CCH * NPIX];       // PAM V, [C,N] bf16
__device__ __nv_bfloat16 g_vcT[BATCH * NPIX * CCH];       // CAM V, [N,C] bf16
__device__ __nv_bfloat16 g_pt[(size_t)BATCH * NPIX * NPIX]; // PAM p~ bf16 (134MB)
__device__ __nv_bfloat16 g_ecb[BATCH * CCH * CCH];        // CAM attn bf16

#define MMA_TF32(acc, af, bf)                                               \
    asm volatile(                                                           \
        "mma.sync.aligned.m16n8k8.row.col.f32.tf32.tf32.f32 "               \
        "{%0,%1,%2,%3},{%4,%5,%6,%7},{%8,%9},{%0,%1,%2,%3};"                \
        : "+f"(acc[0]), "+f"(acc[1]), "+f"(acc[2]), "+f"(acc[3])            \
        : "r"(af[0]), "r"(af[1]), "r"(af[2]), "r"(af[3]),                   \
          "r"(bf[0]), "r"(bf[1]))

#define MMA_BF16(acc, af, bf)                                               \
    asm volatile(                                                           \
        "mma.sync.aligned.m16n8k16.row.col.f32.bf16.bf16.f32 "              \
        "{%0,%1,%2,%3},{%4,%5,%6,%7},{%8,%9},{%0,%1,%2,%3};"                \
        : "+f"(acc[0]), "+f"(acc[1]), "+f"(acc[2]), "+f"(acc[3])            \
        : "r"(af[0]), "r"(af[1]), "r"(af[2]), "r"(af[3]),                   \
          "r"(bf[0]), "r"(bf[1]))

// ---------------- FFMA-pipe exp (x <= 0 path; ~2e-6 rel err) ----------------
__device__ __forceinline__ float fexp(float x)
{
    float t  = fmaxf(x * 1.4426950408889634f, -126.0f);
    float fi = rintf(t);
    float f  = t - fi;
    float p  = 1.3333558146e-3f;
    p = fmaf(p, f, 9.6181291076e-3f);
    p = fmaf(p, f, 5.5504108665e-2f);
    p = fmaf(p, f, 2.4022650696e-1f);
    p = fmaf(p, f, 6.9314718056e-1f);
    p = fmaf(p, f, 1.0f);
    return __int_as_float(__float_as_int(p) + (((int)fi) << 23));
}

// =====================================================================
// tf32 tensor-core GEMM body.  C[M,N] = A*B.
// TA: A stored [K,M]; else [M,K].  TB: B stored [N,K]; else [K,N].
// BIASR: +bias[m].  BIASC: +bias[n].  OBF: write bf16 else fp32.
// =====================================================================
template<bool TA, bool TB, bool BIASR, bool BIASC, bool OBF>
__device__ __forceinline__ void
gemm_body(const float* __restrict__ Ab, const float* __restrict__ Bb,
          const float* __restrict__ bias, void* Cb,
          int M, int N, int K, int bm, int bn)
{
    constexpr int BK = 16;
    __shared__ uint32_t As[2][BK][128 + 8];
    __shared__ uint32_t Bs[2][BK][128 + 8];

    const int tid = threadIdx.x;
    const int lane = tid & 31;
    const int grp  = lane >> 2;
    const int tig  = lane & 3;
    const int warpId = tid >> 5;
    const int warpM  = warpId >> 2;
    const int warpN  = warpId & 3;

    float acc[4][4][4];
#pragma unroll
    for (int mi = 0; mi < 4; mi++)
#pragma unroll
        for (int ni = 0; ni < 4; ni++)
#pragma unroll
            for (int r = 0; r < 4; r++) acc[mi][ni][r] = 0.0f;

    float4 ra[2], rb[2];

    auto ldA = [&](int k0) {
#pragma unroll
        for (int i = 0; i < 2; i++) {
            int idx = tid + i * 256;
            if (TA) {
                int k = idx >> 5, m4 = idx & 31;
                int gm = bm + m4 * 4;
                ra[i] = (gm < M)
                    ? *reinterpret_cast<const float4*>(Ab + (long long)(k0 + k) * M + gm)
                    : make_float4(0.f, 0.f, 0.f, 0.f);
            } else {
                int m = idx >> 2, k4 = idx & 3;
                int gm = bm + m;
                ra[i] = (gm < M)
                    ? *reinterpret_cast<const float4*>(Ab + (long long)gm * K + k0 + k4 * 4)
                    : make_float4(0.f, 0.f, 0.f, 0.f);
            }
        }
    };
    auto stA = [&](int buf) {
#pragma unroll
        for (int i = 0; i < 2; i++) {
            int idx = tid + i * 256;
            float v[4] = {ra[i].x, ra[i].y, ra[i].z, ra[i].w};
            if (TA) {
                int k = idx >> 5, m4 = idx & 31;
#pragma unroll
                for (int j = 0; j < 4; j++) As[buf][k][m4 * 4 + j] = __float_as_uint(v[j]);
            } else {
                int m = idx >> 2, k4 = idx & 3;
#pragma unroll
                for (int j = 0; j < 4; j++) As[buf][k4 * 4 + j][m] = __float_as_uint(v[j]);
            }
        }
    };
    auto ldB = [&](int k0) {
#pragma unroll
        for (int i = 0; i < 2; i++) {
            int idx = tid + i * 256;
            if (TB) {
                int n = idx >> 2, k4 = idx & 3;
                rb[i] = *reinterpret_cast<const float4*>(Bb + (long long)(bn + n) * K + k0 + k4 * 4);
            } else {
                int k = idx >> 5, n4 = idx & 31;
                rb[i] = *reinterpret_cast<const float4*>(Bb + (long long)(k0 + k) * N + bn + n4 * 4);
            }
        }
    };
    auto stB = [&](int buf) {
#pragma unroll
        for (int i = 0; i < 2; i++) {
            int idx = tid + i * 256;
            float v[4] = {rb[i].x, rb[i].y, rb[i].z, rb[i].w};
            if (TB) {
                int n = idx >> 2, k4 = idx & 3;
#pragma unroll
                for (int j = 0; j < 4; j++) Bs[buf][k4 * 4 + j][n] = __float_as_uint(v[j]);
            } else {
                int k = idx >> 5, n4 = idx & 31;
#pragma unroll
                for (int j = 0; j < 4; j++) Bs[buf][k][n4 * 4 + j] = __float_as_uint(v[j]);
            }
        }
    };
    auto compute = [&](int buf) {
#pragma unroll
        for (int ks = 0; ks < BK; ks += 8) {
            uint32_t af[4][4], bf[4][2];
#pragma unroll
            for (int mi = 0; mi < 4; mi++) {
                int mB = warpM * 64 + mi * 16;
                af[mi][0] = As[buf][ks + tig    ][mB + grp];
                af[mi][1] = As[buf][ks + tig    ][mB + grp + 8];
                af[mi][2] = As[buf][ks + tig + 4][mB + grp];
                af[mi][3] = As[buf][ks + tig + 4][mB + grp + 8];
            }
#pragma unroll
            for (int ni = 0; ni < 4; ni++) {
                int nB = warpN * 32 + ni * 8;
                bf[ni][0] = Bs[buf][ks + tig    ][nB + grp];
                bf[ni][1] = Bs[buf][ks + tig + 4][nB + grp];
            }
#pragma unroll
            for (int mi = 0; mi < 4; mi++)
#pragma unroll
                for (int ni = 0; ni < 4; ni++)
                    MMA_TF32(acc[mi][ni], af[mi], bf[ni]);
        }
    };

    const int NT = K / BK;
    ldA(0); ldB(0);
    stA(0); stB(0);
    __syncthreads();
    for (int it = 0; it < NT; ++it) {
        int buf = it & 1;
        if (it + 1 < NT) { ldA((it + 1) * BK); ldB((it + 1) * BK); }
        compute(buf);
        if (it + 1 < NT) { stA(buf ^ 1); stB(buf ^ 1); }
        __syncthreads();
    }

#pragma unroll
    for (int mi = 0; mi < 4; mi++) {
#pragma unroll
        for (int half = 0; half < 2; half++) {
            int gm = bm + warpM * 64 + mi * 16 + grp + half * 8;
            if (gm >= M) continue;
            float bv = BIASR ? bias[gm] : 0.0f;
#pragma unroll
            for (int ni = 0; ni < 4; ni++) {
                int gn = bn + warpN * 32 + ni * 8 + tig * 2;
                float vx = acc[mi][ni][half * 2 + 0] + bv;
                float vy = acc[mi][ni][half * 2 + 1] + bv;
                if (BIASC) { vx += bias[gn]; vy += bias[gn + 1]; }
                if (OBF) {
                    __nv_bfloat16* crow = (__nv_bfloat16*)Cb + (long long)gm * N;
                    *reinterpret_cast<__nv_bfloat162*>(&crow[gn]) =
                        __floats2bfloat162_rn(vx, vy);
                } else {
                    float* crow = (float*)Cb + (long long)gm * N;
                    *reinterpret_cast<float2*>(&crow[gn]) = make_float2(vx, vy);
                }
            }
        }
    }
}

template<bool TA, bool TB, bool BIASR, bool BIASC, bool OBF>
__global__ void __launch_bounds__(256, 2)
gemm_tc_k(const float* __restrict__ A, const float* __restrict__ B,
          const float* __restrict__ bias, void* C,
          int M, int N, int K,
          long long aStr, long long bStr, long long cStr)
{
    void* Cb = OBF ? (void*)((__nv_bfloat16*)C + (long long)blockIdx.z * cStr)
                   : (void*)((float*)C + (long long)blockIdx.z * cStr);
    gemm_body<TA, TB, BIASR, BIASC, OBF>(
        A + (long long)blockIdx.z * aStr, B + (long long)blockIdx.z * bStr,
        bias, Cb, M, N, K, blockIdx.y * 128, blockIdx.x * 128);
}

// 4 small projections (M=64) fused into one launch
__global__ void __launch_bounds__(256, 2)
quad_proj_k(const float* __restrict__ x,
            const float* w0, const float* b0, float* o0,
            const float* w1, const float* b1, float* o1,
            const float* w2, const float* b2, float* o2,
            const float* w3, const float* b3, float* o3)
{
    const float* W; const float* bia; float* O;
    switch (blockIdx.y) {
        case 0:  W = w0; bia = b0; O = o0; break;
        case 1:  W = w1; bia = b1; O = o1; break;
        case 2:  W = w2; bia = b2; O = o2; break;
        default: W = w3; bia = b3; O = o3; break;
    }
    const float* xb = x + (long long)blockIdx.z * (CCH * NPIX);
    float* Ob = O + (long long)blockIdx.z * (C8 * NPIX);
    gemm_body<false, false, true, false, false>(W, xb, bia, Ob,
        C8, NPIX, CCH, 0, blockIdx.x * 128);
}

// =====================================================================
// PAM energy + tile softmax:  S = Q^T K (tf32, K=64), then per-tile row
// max m_t, p~ = exp(S - m_t) written as bf16, row sums s_t. Stats to gmem.
// =====================================================================
__global__ void __launch_bounds__(256, 2)
pam_energy_p(const float* __restrict__ qp, const float* __restrict__ kp,
             __nv_bfloat16* __restrict__ Pt,
             float* __restrict__ gmax, float* __restrict__ gsum)
{
    constexpr int BK = 16;
    __shared__ uint32_t As[2][BK][128 + 8];
    __shared__ uint32_t Bs[2][BK][128 + 8];
    __shared__ float smx[4][128];
    __shared__ float sms[4][128];
    __shared__ float sm_m[128];

    const long long qStr = (long long)C8 * NPIX;
    const float* Ab = qp + (long long)blockIdx.z * qStr;   // [64, 4096]
    const float* Bb = kp + (long long)blockIdx.z * qStr;   // [64, 4096]
    const int bm = blockIdx.y * 128;   // q
    const int bn = blockIdx.x * 128;   // k

    const int tid = threadIdx.x;
    const int lane = tid & 31;
    const int grp  = lane >> 2;
    const int tig  = lane & 3;
    const int warpId = tid >> 5;
    const int warpM  = warpId >> 2;
    const int warpN  = warpId & 3;

    float acc[4][4][4];
#pragma unroll
    for (int mi = 0; mi < 4; mi++)
#pragma unroll
        for (int ni = 0; ni < 4; ni++)
#pragma unroll
            for (int r = 0; r < 4; r++) acc[mi][ni][r] = 0.0f;

    float4 ra[2], rb[2];
    auto ldA = [&](int k0) {
#pragma unroll
        for (int i = 0; i < 2; i++) {
            int idx = tid + i * 256;
            int k = idx >> 5, m4 = idx & 31;
            ra[i] = *reinterpret_cast<const float4*>(Ab + (long long)(k0 + k) * NPIX + bm + m4 * 4);
        }
    };
    auto stA = [&](int buf) {
#pragma unroll
        for (int i = 0; i < 2; i++) {
            int idx = tid + i * 256;
            int k = idx >> 5, m4 = idx & 31;
            float v[4] = {ra[i].x, ra[i].y, ra[i].z, ra[i].w};
#pragma unroll
            for (int j = 0; j < 4; j++) As[buf][k][m4 * 4 + j] = __float_as_uint(v[j]);
        }
    };
    auto ldB = [&](int k0) {
#pragma unroll
        for (int i = 0; i < 2; i++) {
            int idx = tid + i * 256;
            int k = idx >> 5, n4 = idx & 31;
            rb[i] = *reinterpret_cast<const float4*>(Bb + (long long)(k0 + k) * NPIX + bn + n4 * 4);
        }
    };
    auto stB = [&](int buf) {
#pragma unroll
        for (int i = 0; i < 2; i++) {
            int idx = tid + i * 256;
            int k = idx >> 5, n4 = idx & 31;
            float v[4] = {rb[i].x, rb[i].y, rb[i].z, rb[i].w};
#pragma unroll
            for (int j = 0; j < 4; j++) Bs[buf][k][n4 * 4 + j] = __float_as_uint(v[j]);
        }
    };
    auto compute = [&](int buf) {
#pragma unroll
        for (int ks = 0; ks < BK; ks += 8) {
            uint32_t af[4][4], bf[4][2];
#pragma unroll
            for (int mi = 0; mi < 4; mi++) {
                int mB = warpM * 64 + mi * 16;
                af[mi][0] = As[buf][ks + tig    ][mB + grp];
                af[mi][1] = As[buf][ks + tig    ][mB + grp + 8];
                af[mi][2] = As[buf][ks + tig + 4][mB + grp];
                af[mi][3] = As[buf][ks + tig + 4][mB + grp + 8];
            }
#pragma unroll
            for (int ni = 0; ni < 4; ni++) {
                int nB = warpN * 32 + ni * 8;
                bf[ni][0] = Bs[buf][ks + tig    ][nB + grp];
                bf[ni][1] = Bs[buf][ks + tig + 4][nB + grp];
            }
#pragma unroll
            for (int mi = 0; mi < 4; mi++)
#pragma unroll
                for (int ni = 0; ni < 4; ni++)
                    MMA_TF32(acc[mi][ni], af[mi], bf[ni]);
        }
    };

    const int NT = C8 / BK;   // 4
    ldA(0); ldB(0);
    stA(0); stB(0);
    __syncthreads();
    for (int it = 0; it < NT; ++it) {
        int buf = it & 1;
        if (it + 1 < NT) { ldA((it + 1) * BK); ldB((it + 1) * BK); }
        compute(buf);
        if (it + 1 < NT) { stA(buf ^ 1); stB(buf ^ 1); }
        __syncthreads();
    }

    // ---- tile row maxima ----
#pragma unroll
    for (int mi = 0; mi < 4; mi++) {
#pragma unroll
        for (int half = 0; half < 2; half++) {
            int rl = warpM * 64 + mi * 16 + grp + half * 8;
            float v = -3.0e38f;
#pragma unroll
            for (int ni = 0; ni < 4; ni++)
                v = fmaxf(v, fmaxf(acc[mi][ni][half * 2], acc[mi][ni][half * 2 + 1]));
            v = fmaxf(v, __shfl_xor_sync(0xffffffffu, v, 1));
            v = fmaxf(v, __shfl_xor_sync(0xffffffffu, v, 2));
            if (tig == 0) smx[warpN][rl] = v;
        }
    }
    __syncthreads();
    if (tid < 128)
        sm_m[tid] = fmaxf(fmaxf(smx[0][tid], smx[1][tid]),
                          fmaxf(smx[2][tid], smx[3][tid]));
    __syncthreads();

    // ---- exp + tile row sums (acc overwritten with p~) ----
#pragma unroll
    for (int mi = 0; mi < 4; mi++) {
#pragma unroll
        for (int half = 0; half < 2; half++) {
            int rl = warpM * 64 + mi * 16 + grp + half * 8;
            float m = sm_m[rl];
            float part = 0.0f;
#pragma unroll
            for (int ni = 0; ni < 4; ni++) {
#pragma unroll
                for (int e = 0; e < 2; e++) {
                    float pval = fexp(acc[mi][ni][half * 2 + e] - m);
                    acc[mi][ni][half * 2 + e] = pval;
                    part += pval;
                }
            }
            part += __shfl_xor_sync(0xffffffffu, part, 1);
            part += __shfl_xor_sync(0xffffffffu, part, 2);
            if (tig == 0) sms[warpN][rl] = part;
        }
    }
    __syncthreads();
    if (tid < 128) {
        long long o = ((long long)blockIdx.z * NKT + blockIdx.x) * NPIX + bm + tid;
        gmax[o] = sm_m[tid];
        gsum[o] = sms[0][tid] + sms[1][tid] + sms[2][tid] + sms[3][tid];
    }

    // ---- write p~ as bf16 [q, k] ----
    __nv_bfloat16* Pb = Pt + (long long)blockIdx.z * NPIX * NPIX;
#pragma unroll
    for (int mi = 0; mi < 4; mi++) {
#pragma unroll
        for (int half = 0; half < 2; half++) {
            int gm = bm + warpM * 64 + mi * 16 + grp + half * 8;
            __nv_bfloat16* crow = Pb + (long long)gm * NPIX;
#pragma unroll
            for (int ni = 0; ni < 4; ni++) {
                int gn = bn + warpN * 32 + ni * 8 + tig * 2;
                *reinterpret_cast<__nv_bfloat162*>(&crow[gn]) =
                    __floats2bfloat162_rn(acc[mi][ni][half * 2], acc[mi][ni][half * 2 + 1]);
            }
        }
    }
}

// =====================================================================
// bf16 NT GEMM: C[M,N] = A[M,K] * B[N,K]^T, fp32 out.
// SCALEB: B rows are p~; scale each loaded element by f[kt][row] where
//         f = exp(m_t - m_row)/l_row, built in the prologue from stats.
// FINAL:  epilogue writes 2*x + gp*outp + gc*acc (the module output).
// =====================================================================
template<bool SCALEB, bool FINAL>
__global__ void __launch_bounds__(256, 2)
gemm_bf16_nt(const __nv_bfloat16* __restrict__ A, const __nv_bfloat16* __restrict__ B,
             float* __restrict__ C,
             const float* __restrict__ gmax, const float* __restrict__ gsum,
             const float* __restrict__ xres, const float* __restrict__ outp,
             const float* __restrict__ pg, const float* __restrict__ cg,
             int M, int N, int K,
             long long aStr, long long bStr, long long cStr)
{
    __shared__ uint32_t Ap[2][16][128 + 8];
    __shared__ uint32_t Bp[2][16][128 + 8];
    __shared__ __half sm_f[SCALEB ? 32 : 1][SCALEB ? 128 : 1];

    const __nv_bfloat16* Ab = A + (long long)blockIdx.z * aStr;
    const __nv_bfloat16* Bb = B + (long long)blockIdx.z * bStr;
    float* Cb = C + (long long)blockIdx.z * cStr;

    const int bm = blockIdx.y * 128;
    const int bn = blockIdx.x * 128;
    const int tid = threadIdx.x;
    const int lane = tid & 31;
    const int grp  = lane >> 2;
    const int tig  = lane & 3;
    const int warpId = tid >> 5;
    const int warpM  = warpId >> 2;
    const int warpN  = warpId & 3;

    if (SCALEB) {
        if (tid < 128) {
            const float* gm_ = gmax + (long long)blockIdx.z * NKT * NPIX + bn + tid;
            const float* gs_ = gsum + (long long)blockIdx.z * NKT * NPIX + bn + tid;
            float mq = -3.0e38f;
#pragma unroll
            for (int kt = 0; kt < NKT; kt++) mq = fmaxf(mq, gm_[kt * NPIX]);
            float l = 0.0f;
            float ev[NKT];
#pragma unroll
            for (int kt = 0; kt < NKT; kt++) {
                ev[kt] = fexp(gm_[kt * NPIX] - mq);
                l += ev[kt] * gs_[kt * NPIX];
            }
            float inv = 1.0f / l;
#pragma unroll
            for (int kt = 0; kt < NKT; kt++)
                sm_f[kt][tid] = __float2half(ev[kt] * inv);
        }
        __syncthreads();
    }

    float acc[4][4][4];
#pragma unroll
    for (int mi = 0; mi < 4; mi++)
#pragma unroll
        for (int ni = 0; ni < 4; ni++)
#pragma unroll
            for (int r = 0; r < 4; r++) acc[mi][ni][r] = 0.0f;

    uint4 ra[2], rb[2];
    int ktld = 0;

    auto ldA = [&](int k0) {
#pragma unroll
        for (int i = 0; i < 2; i++) {
            int idx = tid + i * 256;
            int m = idx >> 2, kg = idx & 3;
            int gm = bm + m;
            ra[i] = (gm < M)
                ? *reinterpret_cast<const uint4*>(Ab + (long long)gm * K + k0 + kg * 8)
                : make_uint4(0u, 0u, 0u, 0u);
        }
    };
    auto stA = [&](int buf) {
#pragma unroll
        for (int i = 0; i < 2; i++) {
            int idx = tid + i * 256;
            int m = idx >> 2, kg = idx & 3;
            Ap[buf][kg * 4 + 0][m] = ra[i].x;
            Ap[buf][kg * 4 + 1][m] = ra[i].y;
            Ap[buf][kg * 4 + 2][m] = ra[i].z;
            Ap[buf][kg * 4 + 3][m] = ra[i].w;
        }
    };
    auto ldB = [&](int k0) {
        if (SCALEB) ktld = k0 >> 7;
#pragma unroll
        for (int i = 0; i < 2; i++) {
            int idx = tid + i * 256;
            int n = idx >> 2, kg = idx & 3;
            rb[i] = *reinterpret_cast<const uint4*>(Bb + (long long)(bn + n) * K + k0 + kg * 8);
        }
    };
    auto scale_pair = [&](uint32_t u, float f) -> uint32_t {
        __nv_bfloat162 h = *reinterpret_cast<__nv_bfloat162*>(&u);
        float2 v = __bfloat1622float2(h);
        __nv_bfloat162 r = __floats2bfloat162_rn(v.x * f, v.y * f);
        return *reinterpret_cast<uint32_t*>(&r);
    };
    auto stB = [&](int buf) {
#pragma unroll
        for (int i = 0; i < 2; i++) {
            int idx = tid + i * 256;
            int n = idx >> 2, kg = idx & 3;
            uint32_t w[4] = {rb[i].x, rb[i].y, rb[i].z, rb[i].w};
            if (SCALEB) {
                float f = __half2float(sm_f[ktld][n]);
#pragma unroll
                for (int j = 0; j < 4; j++) w[j] = scale_pair(w[j], f);
            }
#pragma unroll
            for (int j = 0; j < 4; j++) Bp[buf][kg * 4 + j][n] = w[j];
        }
    };
    auto compute = [&](int buf) {
#pragma unroll
        for (int c = 0; c < 2; c++) {
            const int pb = c * 8;
            uint32_t af[4][4], bf[4][2];
#pragma unroll
            for (int mi = 0; mi < 4; mi++) {
                int mB = warpM * 64 + mi * 16;
                af[mi][0] = Ap[buf][pb + tig    ][mB + grp];
                af[mi][1] = Ap[buf][pb + tig    ][mB + grp + 8];
                af[mi][2] = Ap[buf][pb + tig + 4][mB + grp];
                af[mi][3] = Ap[buf][pb + tig + 4][mB + grp + 8];
            }
#pragma unroll
            for (int ni = 0; ni < 4; ni++) {
                int nB = warpN * 32 + ni * 8;
                bf[ni][0] = Bp[buf][pb + tig    ][nB + grp];
                bf[ni][1] = Bp[buf][pb + tig + 4][nB + grp];
            }
#pragma unroll
            for (int mi = 0; mi < 4; mi++)
#pragma unroll
                for (int ni = 0; ni < 4; ni++)
                    MMA_BF16(acc[mi][ni], af[mi], bf[ni]);
        }
    };

    const int NT = K / 32;
    ldA(0); ldB(0);
    stA(0); stB(0);
    __syncthreads();
    for (int it = 0; it < NT; ++it) {
        int buf = it & 1;
        if (it + 1 < NT) { ldA((it + 1) * 32); ldB((it + 1) * 32); }
        compute(buf);
        if (it + 1 < NT) { stA(buf ^ 1); stB(buf ^ 1); }
        __syncthreads();
    }

    float gpv = 0.f, gcv = 0.f;
    const float* xb = nullptr;
    const float* ob = nullptr;
    if (FINAL) {
        gpv = pg[0]; gcv = cg[0];
        xb = xres + (long long)blockIdx.z * cStr;
        ob = outp + (long long)blockIdx.z * cStr;
    }

#pragma unroll
    for (int mi = 0; mi < 4; mi++) {
#pragma unroll
        for (int half = 0; half < 2; half++) {
            int gm = bm + warpM * 64 + mi * 16 + grp + half * 8;
            if (gm >= M) continue;
            float* crow = Cb + (long long)gm * N;
#pragma unroll
            for (int ni = 0; ni < 4; ni++) {
                int gn = bn + warpN * 32 + ni * 8 + tig * 2;
                float vx = acc[mi][ni][half * 2 + 0];
                float vy = acc[mi][ni][half * 2 + 1];
                if (FINAL) {
                    float2 xv = *reinterpret_cast<const float2*>(&xb[(long long)gm * N + gn]);
                    float2 pv = *reinterpret_cast<const float2*>(&ob[(long long)gm * N + gn]);
                    vx = 2.0f * xv.x + gpv * pv.x + gcv * vx;
                    vy = 2.0f * xv.y + gpv * pv.y + gcv * vy;
                }
                *reinterpret_cast<float2*>(&crow[gn]) = make_float2(vx, vy);
            }
        }
    }
}

// -------- CAM row softmax: fp32 in -> bf16 out, softmax(rowmax - e) ----
__global__ void __launch_bounds__(256)
softmax_bf16(const float* __restrict__ in, __nv_bfloat16* __restrict__ out, int n)
{
    __shared__ float buf[512];
    __shared__ float red[8];
    __shared__ float bcast;
    const long long row = blockIdx.x;
    const float* p = in + row * (long long)n;
    const int tid = threadIdx.x;
    const int lane = tid & 31, wid = tid >> 5;

    float m = 3.0e38f;
    for (int i = tid; i < n; i += 256) {
        float v = p[i];
        buf[i] = v;
        m = fminf(m, v);
    }
#pragma unroll
    for (int o = 16; o > 0; o >>= 1)
        m = fminf(m, __shfl_xor_sync(0xffffffffu, m, o));
    if (lane == 0) red[wid] = m;
    __syncthreads();
    if (wid == 0) {
        float v = (lane < 8) ? red[lane] : 3.0e38f;
#pragma unroll
        for (int o = 4; o > 0; o >>= 1)
            v = fminf(v, __shfl_xor_sync(0xffffffffu, v, o));
        if (lane == 0) bcast = v;
    }
    __syncthreads();
    const float mx = bcast;

    float s = 0.0f;
    for (int i = tid; i < n; i += 256) {
        float e = fexp(mx - buf[i]);
        buf[i] = e;
        s += e;
    }
#pragma unroll
    for (int o = 16; o > 0; o >>= 1) s += __shfl_xor_sync(0xffffffffu, s, o);
    if (lane == 0) red[wid] = s;
    __syncthreads();
    if (wid == 0) {
        float v = (lane < 8) ? red[lane] : 0.0f;
#pragma unroll
        for (int o = 4; o > 0; o >>= 1) v += __shfl_xor_sync(0xffffffffu, v, o);
        if (lane == 0) bcast = v;
    }
    __syncthreads();
    const float inv = 1.0f / bcast;
    __nv_bfloat162* o2 = reinterpret_cast<__nv_bfloat162*>(out + row * (long long)n);
    for (int i = tid * 2; i < n; i += 512)
        o2[i >> 1] = __floats2bfloat162_rn(buf[i] * inv, buf[i + 1] * inv);
}

// ---------------- launch ----------------
extern "C" void kernel_launch(void* const* d_in, const int* in_sizes, int n_in,
                              void* d_out, int out_size)
{
    (void)in_sizes; (void)n_in; (void)out_size;
    const float* x       = (const float*)d_in[0];
    const float* pam_wq  = (const float*)d_in[1];
    const float* pam_bq  = (const float*)d_in[2];
    const float* pam_wk  = (const float*)d_in[3];
    const float* pam_bk  = (const float*)d_in[4];
    const float* pam_wv  = (const float*)d_in[5];
    const float* pam_bv  = (const float*)d_in[6];
    const float* pam_g   = (const float*)d_in[7];
    const float* cam_wq  = (const float*)d_in[8];
    const float* cam_bq  = (const float*)d_in[9];
    const float* cam_wk  = (const float*)d_in[10];
    const float* cam_bk  = (const float*)d_in[11];
    const float* cam_wv  = (const float*)d_in[12];
    const float* cam_bv  = (const float*)d_in[13];
    const float* cam_g   = (const float*)d_in[14];

    float *qp, *kp, *qc, *kc, *gmax, *gsum, *ec, *outp;
    __nv_bfloat16 *vp, *vcT, *pt, *ecb;
    cudaGetSymbolAddress((void**)&qp,   g_qp);
    cudaGetSymbolAddress((void**)&kp,   g_kp);
    cudaGetSymbolAddress((void**)&qc,   g_qc);
    cudaGetSymbolAddress((void**)&kc,   g_kc);
    cudaGetSymbolAddress((void**)&gmax, g_maxp);
    cudaGetSymbolAddress((void**)&gsum, g_sump);
    cudaGetSymbolAddress((void**)&ec,   g_ec);
    cudaGetSymbolAddress((void**)&outp, g_outp);
    cudaGetSymbolAddress((void**)&vp,   g_vp);
    cudaGetSymbolAddress((void**)&vcT,  g_vcT);
    cudaGetSymbolAddress((void**)&pt,   g_pt);
    cudaGetSymbolAddress((void**)&ecb,  g_ecb);

    const long long xStr  = (long long)CCH * NPIX;
    const long long vStr  = (long long)CCH * NPIX;
    const long long vTStr = (long long)NPIX * CCH;
    const long long aStrP = (long long)NPIX * NPIX;
    const long long eStrC = (long long)CCH * CCH;
    const long long qStr  = (long long)C8 * NPIX;

    dim3 blk(256);

    // ---- 1a. four small projections (q/k for PAM & CAM) ----
    quad_proj_k<<<dim3(NPIX / 128, 4, BATCH), blk>>>(x,
        pam_wq, pam_bq, qp,  pam_wk, pam_bk, kp,
        cam_wq, cam_bq, qc,  cam_wk, cam_bk, kc);

    // ---- 1b. PAM V projection -> bf16 [C, N] ----
    gemm_tc_k<false, false, true, false, true><<<dim3(NPIX / 128, CCH / 128, BATCH), blk>>>(
        pam_wv, x, pam_bv, vp, CCH, NPIX, CCH, 0, xStr, vStr);

    // ---- 1c. CAM V projection, transposed output -> bf16 [N, C] ----
    gemm_tc_k<true, true, false, true, true><<<dim3(CCH / 128, NPIX / 128, BATCH), blk>>>(
        x, cam_wv, cam_bv, vcT, NPIX, CCH, CCH, xStr, 0, vTStr);

    // ---- 2. PAM energy + tile softmax -> p~ bf16 + stats ----
    pam_energy_p<<<dim3(NPIX / 128, NPIX / 128, BATCH), blk>>>(qp, kp, pt, gmax, gsum);

    // ---- 3. PAM AV with scaled-B softmax completion ----
    gemm_bf16_nt<true, false><<<dim3(NPIX / 128, CCH / 128, BATCH), blk>>>(
        vp, pt, outp, gmax, gsum, nullptr, nullptr, nullptr, nullptr,
        CCH, NPIX, NPIX, vStr, aStrP, vStr);

    // ---- 4. CAM energy (NT tf32, fp32 out) ----
    gemm_tc_k<false, true, false, false, false><<<dim3(CCH / 128, CCH / 128, BATCH), blk>>>(
        qc, kc, nullptr, ec, CCH, CCH, CCH, qStr, qStr, eStrC);

    // ---- 5. CAM softmax (flipped) -> bf16 ----
    softmax_bf16<<<BATCH * CCH, 256>>>(ec, ecb, CCH);

    // ---- 6. CAM AV + final combine -> d_out ----
    gemm_bf16_nt<false, true><<<dim3(NPIX / 128, CCH / 128, BATCH), blk>>>(
        ecb, vcT, (float*)d_out, nullptr, nullptr, x, outp, pam_g, cam_g,
        CCH, NPIX, CCH, eStrC, vTStr, vStr);
}